// round 1
// baseline (speedup 1.0000x reference)
#include <cuda_runtime.h>
#include <math.h>

// ---------------------------------------------------------------------------
// GlobalMHSAWithPosBias: B=128, C=512, RES=14 (N=196), HEADS=8, hd=64
//   qkv  = BN1(qkv_w @ x)            -> q,k,v  [B,8,64,196]
//   attn = softmax(q^T k * 0.125 + bias[h, idxs])
//   o    = attn @ v^T                -> (B,8,196,64) RAW-reshaped to (B,512,196)
//   out  = BN2(proj_w @ gelu(o))
// ---------------------------------------------------------------------------

#define B_    128
#define CIN   512
#define NQ    196
#define NPAD  224          // 4 * 56
#define HEADS 8
#define HD    64
#define EPS_  1e-5f

// scratch (device globals: allocation-free rule). BSS is zero-initialized, so
// padding columns of g_att (never written) are 0 forever.
__device__ float g_xp  [(size_t)B_ * CIN * NPAD];        // padded input
__device__ float g_qkv [(size_t)B_ * 3 * CIN * NPAD];    // qkv, BN1 applied
__device__ float g_att [(size_t)B_ * CIN * NPAD];        // gelu(o), scrambled layout
__device__ float g_biasT[HEADS * NQ * NQ];               // bias, [h][m][n] (symmetric)

// ---------------------------------------------------------------------------
// pad x: [b][c][196] -> [b][c][224], zero-fill pad
// ---------------------------------------------------------------------------
__global__ void pad_x_kernel(const float* __restrict__ x) {
    int i = blockIdx.x * blockDim.x + threadIdx.x;
    const int total = B_ * CIN * NPAD;
    if (i >= total) return;
    int n  = i % NPAD;
    int rc = i / NPAD;
    g_xp[i] = (n < NQ) ? x[(size_t)rc * NQ + n] : 0.f;
}

// ---------------------------------------------------------------------------
// bias gather. idxs may be int32 or int64 (detected: true idx[1]=1, idx[3]=3,
// so zero words at 1 and 3 imply int64 low/high word pairs).
// idx matrix is symmetric -> storing [h][m][n] equals [h][n][m].
// ---------------------------------------------------------------------------
__global__ void gather_bias_kernel(const float* __restrict__ ab,
                                   const int*   __restrict__ idxs) {
    int i = blockIdx.x * blockDim.x + threadIdx.x;
    const int total = HEADS * NQ * NQ;
    if (i >= total) return;
    int stride = (idxs[1] == 0 && idxs[3] == 0) ? 2 : 1;   // int64 detection
    int h = i / (NQ * NQ);
    int j = i - h * (NQ * NQ);
    g_biasT[i] = ab[h * NQ + idxs[(size_t)j * stride]];
}

// ---------------------------------------------------------------------------
// Tiled fp32 GEMM + fused BN affine.
//   Y[b][o][n] = (sum_c W[o][c] * X[b][c][n]) * inv[o] + shift[o]
// BM=128, BN=56, BK=16, 224 threads, 8x4 microtile. N padded to 224 -> exact.
// MODE 0: X=g_xp,  Y=g_qkv (O=1536, ldy=224, no guard)
// MODE 1: X=g_att, Y=out   (O=512,  ldy=196, guard n<196)
// ---------------------------------------------------------------------------
template <int MODE>
__global__ __launch_bounds__(224)
void gemm_affine(const float* __restrict__ W,
                 const float* __restrict__ gamma, const float* __restrict__ beta,
                 const float* __restrict__ mean,  const float* __restrict__ var,
                 float* __restrict__ outp) {
    const float* __restrict__ X = (MODE == 0) ? g_xp : g_att;
    float* __restrict__ Y       = (MODE == 0) ? g_qkv : outp;
    const int Ocnt = (MODE == 0) ? 3 * CIN : CIN;
    const int ldy  = (MODE == 0) ? NPAD : NQ;

    __shared__ float Ws[16][128 + 4];   // [k][m] (transposed)
    __shared__ float Xs[16][56 + 4];    // [k][n]

    const int tid = threadIdx.x;
    const int b   = blockIdx.z;
    const int o0  = blockIdx.y * 128;
    const int n0  = blockIdx.x * 56;
    const int tx  = tid % 14;           // 14 n-columns of 4
    const int ty  = tid / 14;           // 16 m-rows of 8

    const float* __restrict__ Wp = W + (size_t)o0 * CIN;
    const float* __restrict__ Xp = X + (size_t)b * CIN * NPAD + n0;

    float acc[8][4];
#pragma unroll
    for (int i = 0; i < 8; i++)
#pragma unroll
        for (int j = 0; j < 4; j++) acc[i][j] = 0.f;

    const int xk = tid / 14;   // X tile: 16 rows x 14 float4 = 224 loads
    const int xj = tid % 14;

    for (int kk = 0; kk < CIN; kk += 16) {
        // W tile: 128 rows x 16 cols = 512 float4
        for (int i = tid; i < 512; i += 224) {
            int r = i >> 2, cg = i & 3;
            float4 w = *(const float4*)(Wp + (size_t)r * CIN + kk + cg * 4);
            Ws[cg * 4 + 0][r] = w.x;
            Ws[cg * 4 + 1][r] = w.y;
            Ws[cg * 4 + 2][r] = w.z;
            Ws[cg * 4 + 3][r] = w.w;
        }
        // X tile: exactly 1 float4 per thread
        {
            float4 xv = *(const float4*)(Xp + (size_t)(kk + xk) * NPAD + xj * 4);
            *(float4*)&Xs[xk][xj * 4] = xv;
        }
        __syncthreads();
#pragma unroll
        for (int k = 0; k < 16; k++) {
            float a[8], bb[4];
            *(float4*)&a[0] = *(const float4*)&Ws[k][ty * 8];
            *(float4*)&a[4] = *(const float4*)&Ws[k][ty * 8 + 4];
            *(float4*)&bb[0] = *(const float4*)&Xs[k][tx * 4];
#pragma unroll
            for (int i = 0; i < 8; i++)
#pragma unroll
                for (int j = 0; j < 4; j++) acc[i][j] += a[i] * bb[j];
        }
        __syncthreads();
    }

#pragma unroll
    for (int i = 0; i < 8; i++) {
        int o = o0 + ty * 8 + i;
        float inv = gamma[o] * rsqrtf(var[o] + EPS_);
        float sh  = beta[o] - mean[o] * inv;
        float* yp = Y + ((size_t)b * Ocnt + o) * ldy + n0;
#pragma unroll
        for (int j = 0; j < 4; j++) {
            int n = tx * 4 + j;
            if (MODE == 0 || (n0 + n) < NQ) yp[n] = acc[i][j] * inv + sh;
        }
    }
}

// ---------------------------------------------------------------------------
// Fused attention: one block per (b,h). Q,K,V [64][196] staged in smem
// (147 KB). Thread n (n<196) owns output row n: online softmax over 7
// m-tiles of 28, then PV accumulation, GELU, and scrambled-reshape store.
// ---------------------------------------------------------------------------
__global__ __launch_bounds__(256)
void attn_kernel() {
    extern __shared__ float sm[];
    float* Qs = sm;                 // [d*196 + n]
    float* Ks = sm + HD * NQ;
    float* Vs = sm + 2 * HD * NQ;

    const int tid = threadIdx.x;
    const int b   = blockIdx.x >> 3;
    const int h   = blockIdx.x & 7;

    const size_t base = ((size_t)b * 3 * CIN + h * HD) * NPAD;
    const float* __restrict__ Qg = g_qkv + base;
    const float* __restrict__ Kg = g_qkv + base + (size_t)CIN * NPAD;
    const float* __restrict__ Vg = g_qkv + base + (size_t)2 * CIN * NPAD;

    for (int i = tid; i < HD * NQ; i += 256) {
        int d = i / NQ, n = i - d * NQ;
        Qs[i] = Qg[(size_t)d * NPAD + n];
        Ks[i] = Kg[(size_t)d * NPAD + n];
        Vs[i] = Vg[(size_t)d * NPAD + n];
    }
    __syncthreads();

    if (tid >= NQ) return;
    const int n = tid;

    float m_run = -1e30f, l_run = 0.f;
    float o[HD];
#pragma unroll
    for (int d = 0; d < HD; d++) o[d] = 0.f;

    const float* __restrict__ bptr = g_biasT + (size_t)h * NQ * NQ;

    for (int mt = 0; mt < 7; mt++) {
        const int m0 = mt * 28;
        float s[28];
#pragma unroll
        for (int m = 0; m < 28; m++) s[m] = 0.f;

        // scores: s[m] = sum_d q[d]*k[d][m0+m]
#pragma unroll 8
        for (int d = 0; d < HD; d++) {
            float qd = Qs[d * NQ + n];
            const float4* kr = (const float4*)(Ks + d * NQ + m0);
#pragma unroll
            for (int m4 = 0; m4 < 7; m4++) {
                float4 kv = kr[m4];
                s[m4 * 4 + 0] += qd * kv.x;
                s[m4 * 4 + 1] += qd * kv.y;
                s[m4 * 4 + 2] += qd * kv.z;
                s[m4 * 4 + 3] += qd * kv.w;
            }
        }
        // scale + bias, tile max
        float tmax = -1e30f;
#pragma unroll
        for (int m = 0; m < 28; m++) {
            s[m] = s[m] * 0.125f + bptr[(size_t)(m0 + m) * NQ + n];
            tmax = fmaxf(tmax, s[m]);
        }
        float mnew = fmaxf(m_run, tmax);
        float corr = __expf(m_run - mnew);
        l_run *= corr;
#pragma unroll
        for (int d = 0; d < HD; d++) o[d] *= corr;
#pragma unroll
        for (int m = 0; m < 28; m++) {
            float p = __expf(s[m] - mnew);
            s[m] = p;
            l_run += p;
        }
        m_run = mnew;

        // o[d] += sum_m p[m] * V[d][m0+m]
#pragma unroll 8
        for (int d = 0; d < HD; d++) {
            const float4* vr = (const float4*)(Vs + d * NQ + m0);
            float accd = o[d];
#pragma unroll
            for (int m4 = 0; m4 < 7; m4++) {
                float4 vv = vr[m4];
                accd += s[m4 * 4 + 0] * vv.x;
                accd += s[m4 * 4 + 1] * vv.y;
                accd += s[m4 * 4 + 2] * vv.z;
                accd += s[m4 * 4 + 3] * vv.w;
            }
            o[d] = accd;
        }
    }

    // normalize + exact GELU + scrambled reshape store:
    //   flat = h*12544 + n*64 + d ; c = flat/196 ; pos = flat%196
    const float linv = 1.f / l_run;
    const int flatbase = h * (NQ * HD) + n * HD;
#pragma unroll
    for (int d = 0; d < HD; d++) {
        float v = o[d] * linv;
        float g = 0.5f * v * (1.f + erff(v * 0.70710678118654752f));
        int flat = flatbase + d;
        int c    = flat / NQ;
        int pos  = flat - c * NQ;
        g_att[((size_t)b * CIN + c) * NPAD + pos] = g;
    }
}

// ---------------------------------------------------------------------------
extern "C" void kernel_launch(void* const* d_in, const int* in_sizes, int n_in,
                              void* d_out, int out_size) {
    const float* x      = (const float*)d_in[0];
    const float* qkv_w  = (const float*)d_in[1];
    const float* bn1_g  = (const float*)d_in[2];
    const float* bn1_b  = (const float*)d_in[3];
    const float* bn1_m  = (const float*)d_in[4];
    const float* bn1_v  = (const float*)d_in[5];
    const float* proj_w = (const float*)d_in[6];
    const float* bn2_g  = (const float*)d_in[7];
    const float* bn2_b  = (const float*)d_in[8];
    const float* bn2_m  = (const float*)d_in[9];
    const float* bn2_v  = (const float*)d_in[10];
    const float* ab     = (const float*)d_in[11];
    const int*   idxs   = (const int*)d_in[12];
    float* out = (float*)d_out;

    const int smem_attn = 3 * HD * NQ * sizeof(float);   // 150528 B
    cudaFuncSetAttribute(attn_kernel,
                         cudaFuncAttributeMaxDynamicSharedMemorySize, smem_attn);

    {   // pad x
        int total = B_ * CIN * NPAD;
        pad_x_kernel<<<(total + 255) / 256, 256>>>(x);
    }
    {   // bias gather
        int total = HEADS * NQ * NQ;
        gather_bias_kernel<<<(total + 255) / 256, 256>>>(ab, idxs);
    }
    {   // QKV GEMM + BN1
        dim3 grid(NPAD / 56, (3 * CIN) / 128, B_);
        gemm_affine<0><<<grid, 224>>>(qkv_w, bn1_g, bn1_b, bn1_m, bn1_v, nullptr);
    }
    {   // attention + gelu + scrambled reshape
        attn_kernel<<<B_ * HEADS, 256, smem_attn>>>();
    }
    {   // proj GEMM + BN2 -> d_out
        dim3 grid(NPAD / 56, CIN / 128, B_);
        gemm_affine<1><<<grid, 224>>>(proj_w, bn2_g, bn2_b, bn2_m, bn2_v, out);
    }
}

// round 2
// speedup vs baseline: 1.7281x; 1.7281x over previous
#include <cuda_runtime.h>
#include <math.h>

// ---------------------------------------------------------------------------
// GlobalMHSAWithPosBias: B=128, C=512, RES=14 (N=196), HEADS=8, hd=64
// Round 2: tf32 mma.sync GEMMs + spill-free split-d attention.
// ---------------------------------------------------------------------------

#define B_    128
#define CIN   512
#define NQ    196
#define NPAD  224          // 4 * 56 = 2 * 112
#define HEADS 8
#define HD    64
#define EPS_  1e-5f

__device__ float g_xp  [(size_t)B_ * CIN * NPAD];        // padded input
__device__ float g_qkv [(size_t)B_ * 3 * CIN * NPAD];    // qkv, BN1 applied
__device__ float g_att [(size_t)B_ * CIN * NPAD];        // gelu(o), scrambled layout
__device__ float g_biasT[HEADS * NQ * NQ];               // bias [h][m][n] (symmetric idx)

// ---------------------------------------------------------------------------
__global__ void pad_x_kernel(const float* __restrict__ x) {
    int i = blockIdx.x * blockDim.x + threadIdx.x;
    const int total = B_ * CIN * NPAD;
    if (i >= total) return;
    int n  = i % NPAD;
    int rc = i / NPAD;
    g_xp[i] = (n < NQ) ? x[(size_t)rc * NQ + n] : 0.f;
}

__global__ void gather_bias_kernel(const float* __restrict__ ab,
                                   const int*   __restrict__ idxs) {
    int i = blockIdx.x * blockDim.x + threadIdx.x;
    const int total = HEADS * NQ * NQ;
    if (i >= total) return;
    int stride = (idxs[1] == 0 && idxs[3] == 0) ? 2 : 1;   // int64 detection
    int h = i / (NQ * NQ);
    int j = i - h * (NQ * NQ);
    g_biasT[i] = ab[h * NQ + idxs[(size_t)j * stride]];
}

// ---------------------------------------------------------------------------
// tf32 helpers
// ---------------------------------------------------------------------------
__device__ __forceinline__ unsigned f2tf32(float f) {
    unsigned u;
    asm("cvt.rna.tf32.f32 %0, %1;" : "=r"(u) : "f"(f));
    return u;
}

__device__ __forceinline__ void mma_tf32(float c[4], const unsigned a[4],
                                         unsigned b0, unsigned b1) {
    asm volatile(
        "mma.sync.aligned.m16n8k8.row.col.f32.tf32.tf32.f32 "
        "{%0,%1,%2,%3}, {%4,%5,%6,%7}, {%8,%9}, {%0,%1,%2,%3};\n"
        : "+f"(c[0]), "+f"(c[1]), "+f"(c[2]), "+f"(c[3])
        : "r"(a[0]), "r"(a[1]), "r"(a[2]), "r"(a[3]), "r"(b0), "r"(b1));
}

// ---------------------------------------------------------------------------
// tf32 tensor-core GEMM + fused BN affine.
//   Y[b][o][n] = (sum_c W[o][c] * X[b][c][n]) * inv[o] + shift[o]
// BM=128, BN=112, BK=32, 256 threads (8 warps, 4m x 2n), warp tile 32x56.
// MODE 0: X=g_xp,  Y=g_qkv (O=1536, ldy=224)   MODE 1: X=g_att, Y=out (O=512, ldy=196)
// ---------------------------------------------------------------------------
#define WPITCH 36
#define XPITCH 120

template <int MODE>
__global__ __launch_bounds__(256)
void gemm_tf32(const float* __restrict__ W,
               const float* __restrict__ gamma, const float* __restrict__ beta,
               const float* __restrict__ mean,  const float* __restrict__ var,
               float* __restrict__ outp) {
    const float* __restrict__ X = (MODE == 0) ? g_xp : g_att;
    float* __restrict__ Y       = (MODE == 0) ? g_qkv : outp;
    const int Ocnt = (MODE == 0) ? 3 * CIN : CIN;
    const int ldy  = (MODE == 0) ? NPAD : NQ;

    __shared__ unsigned Ws[128 * WPITCH];   // [m][k], pitch 36 -> conflict-free frag reads
    __shared__ unsigned Xs[32 * XPITCH];    // [k][n], pitch 120

    const int tid  = threadIdx.x;
    const int lane = tid & 31;
    const int wid  = tid >> 5;
    const int wm   = wid & 3;          // 4 warps in m
    const int wn   = wid >> 2;         // 2 warps in n
    const int m0w  = wm * 32;
    const int n0w  = wn * 56;

    const int b  = blockIdx.z;
    const int o0 = blockIdx.y * 128;
    const int n0 = blockIdx.x * 112;

    const float* __restrict__ Wp = W + (size_t)o0 * CIN;
    const float* __restrict__ Xp = X + (size_t)b * CIN * NPAD + n0;

    float acc[2][7][4];
#pragma unroll
    for (int i = 0; i < 2; i++)
#pragma unroll
        for (int j = 0; j < 7; j++)
#pragma unroll
            for (int k = 0; k < 4; k++) acc[i][j][k] = 0.f;

    const int row = lane >> 2;      // 0..7
    const int col = lane & 3;       // 0..3

    for (int kk = 0; kk < CIN; kk += 32) {
        // W tile: 128 x 32 = 1024 float4 loads
#pragma unroll
        for (int i = tid; i < 1024; i += 256) {
            int r  = i >> 3;
            int c4 = (i & 7) * 4;
            float4 w = *(const float4*)(Wp + (size_t)r * CIN + kk + c4);
            Ws[r * WPITCH + c4 + 0] = f2tf32(w.x);
            Ws[r * WPITCH + c4 + 1] = f2tf32(w.y);
            Ws[r * WPITCH + c4 + 2] = f2tf32(w.z);
            Ws[r * WPITCH + c4 + 3] = f2tf32(w.w);
        }
        // X tile: 32 x 112 = 896 float4 loads
        for (int i = tid; i < 896; i += 256) {
            int r  = i / 28;
            int c4 = (i % 28) * 4;
            float4 xv = *(const float4*)(Xp + (size_t)(kk + r) * NPAD + c4);
            Xs[r * XPITCH + c4 + 0] = f2tf32(xv.x);
            Xs[r * XPITCH + c4 + 1] = f2tf32(xv.y);
            Xs[r * XPITCH + c4 + 2] = f2tf32(xv.z);
            Xs[r * XPITCH + c4 + 3] = f2tf32(xv.w);
        }
        __syncthreads();

#pragma unroll
        for (int ks = 0; ks < 4; ks++) {
            const int k0 = ks * 8;
            unsigned a[2][4];
#pragma unroll
            for (int mt = 0; mt < 2; mt++) {
                int base = (m0w + mt * 16 + row) * WPITCH + k0 + col;
                a[mt][0] = Ws[base];
                a[mt][1] = Ws[base + 8 * WPITCH];
                a[mt][2] = Ws[base + 4];
                a[mt][3] = Ws[base + 8 * WPITCH + 4];
            }
#pragma unroll
            for (int nt = 0; nt < 7; nt++) {
                int bb = (k0 + col) * XPITCH + n0w + nt * 8 + row;
                unsigned b0 = Xs[bb];
                unsigned b1 = Xs[bb + 4 * XPITCH];
                mma_tf32(acc[0][nt], a[0], b0, b1);
                mma_tf32(acc[1][nt], a[1], b0, b1);
            }
        }
        __syncthreads();
    }

    // epilogue: BN affine + store
#pragma unroll
    for (int mt = 0; mt < 2; mt++) {
        int o_a = o0 + m0w + mt * 16 + row;
        int o_b = o_a + 8;
        float inv_a = gamma[o_a] * rsqrtf(var[o_a] + EPS_);
        float sh_a  = beta[o_a] - mean[o_a] * inv_a;
        float inv_b = gamma[o_b] * rsqrtf(var[o_b] + EPS_);
        float sh_b  = beta[o_b] - mean[o_b] * inv_b;
        float* ya = Y + ((size_t)b * Ocnt + o_a) * ldy;
        float* yb = Y + ((size_t)b * Ocnt + o_b) * ldy;
#pragma unroll
        for (int nt = 0; nt < 7; nt++) {
            int c0 = n0 + n0w + nt * 8 + col * 2;
            float y0 = acc[mt][nt][0] * inv_a + sh_a;
            float y1 = acc[mt][nt][1] * inv_a + sh_a;
            float y2 = acc[mt][nt][2] * inv_b + sh_b;
            float y3 = acc[mt][nt][3] * inv_b + sh_b;
            if (MODE == 0) {
                *(float2*)(ya + c0) = make_float2(y0, y1);
                *(float2*)(yb + c0) = make_float2(y2, y3);
            } else {
                if (c0 < NQ)     { ya[c0]     = y0; yb[c0]     = y2; }
                if (c0 + 1 < NQ) { ya[c0 + 1] = y1; yb[c0 + 1] = y3; }
            }
        }
    }
}

// ---------------------------------------------------------------------------
// Attention: one block per (b,h), 448 threads = 196 rows x 2 d-halves.
// No-max softmax (scores are O(1): std~1.3, exp-safe). Per m-tile of 28:
//   score phase: thread (n,g) computes 14 scores, exp -> Pt[n][g*14+j]
//   PV phase:    thread (n,g) accumulates o[d] for d in [g*32, g*32+32)
// Fully static indexing -> no local-memory spills.
// ---------------------------------------------------------------------------
__global__ __launch_bounds__(448)
void attn_kernel() {
    extern __shared__ float sm[];
    float* Qs    = sm;                       // [d][n] 64x196
    float* Ks    = sm + HD * NQ;             // [d][m]
    float* Vs    = sm + 2 * HD * NQ;         // [d][m]
    float* Pt    = sm + 3 * HD * NQ;         // [n][29]
    float* lpart = Pt + NQ * 29;             // [2][196]

    const int tid = threadIdx.x;
    const int g   = tid / 224;               // d-half
    const int n   = tid % 224;               // row (valid if < 196)
    const int b   = blockIdx.x >> 3;
    const int h   = blockIdx.x & 7;

    const size_t base = ((size_t)b * 3 * CIN + h * HD) * NPAD;
    const float* __restrict__ Qg = g_qkv + base;
    const float* __restrict__ Kg = g_qkv + base + (size_t)CIN * NPAD;
    const float* __restrict__ Vg = g_qkv + base + (size_t)2 * CIN * NPAD;

    for (int i = tid; i < HD * NQ; i += 448) {
        int d = i / NQ, m = i - d * NQ;
        Qs[i] = Qg[(size_t)d * NPAD + m];
        Ks[i] = Kg[(size_t)d * NPAD + m];
        Vs[i] = Vg[(size_t)d * NPAD + m];
    }
    __syncthreads();

    const bool act = (n < NQ);
    const float* __restrict__ bptr = g_biasT + (size_t)h * NQ * NQ;

    float o[32];
#pragma unroll
    for (int d = 0; d < 32; d++) o[d] = 0.f;
    float lsum = 0.f;
    const int d0 = g * 32;

    for (int mt = 0; mt < 7; mt++) {
        const int m0 = mt * 28;
        const int mbase = m0 + g * 14;

        if (act) {
            float s[14];
#pragma unroll
            for (int j = 0; j < 14; j++) s[j] = 0.f;
#pragma unroll 4
            for (int d = 0; d < HD; d++) {
                float qd = Qs[d * NQ + n];
                const float2* kr = (const float2*)(Ks + d * NQ + mbase);
#pragma unroll
                for (int j2 = 0; j2 < 7; j2++) {
                    float2 kv = kr[j2];
                    s[2 * j2 + 0] += qd * kv.x;
                    s[2 * j2 + 1] += qd * kv.y;
                }
            }
#pragma unroll
            for (int j = 0; j < 14; j++) {
                int m = mbase + j;
                float sc = s[j] * 0.125f + bptr[(size_t)m * NQ + n];
                float p  = __expf(sc);
                Pt[n * 29 + g * 14 + j] = p;
                lsum += p;
            }
        }
        __syncthreads();

        if (act) {
            float p[28];
#pragma unroll
            for (int j = 0; j < 28; j++) p[j] = Pt[n * 29 + j];
#pragma unroll
            for (int dd = 0; dd < 32; dd++) {
                const float4* vr = (const float4*)(Vs + (d0 + dd) * NQ + m0);
                float accd = o[dd];
#pragma unroll
                for (int j4 = 0; j4 < 7; j4++) {
                    float4 vv = vr[j4];
                    accd += p[4 * j4 + 0] * vv.x;
                    accd += p[4 * j4 + 1] * vv.y;
                    accd += p[4 * j4 + 2] * vv.z;
                    accd += p[4 * j4 + 3] * vv.w;
                }
                o[dd] = accd;
            }
        }
        __syncthreads();
    }

    if (act) lpart[g * NQ + n] = lsum;
    __syncthreads();

    if (act) {
        const float linv = 1.f / (lpart[n] + lpart[NQ + n]);
        const int flatbase = h * (NQ * HD) + n * HD + d0;
#pragma unroll
        for (int dd = 0; dd < 32; dd++) {
            float v = o[dd] * linv;
            float gl = 0.5f * v * (1.f + erff(v * 0.70710678118654752f));
            int flat = flatbase + dd;
            int c    = flat / NQ;
            int pos  = flat - c * NQ;
            g_att[((size_t)b * CIN + c) * NPAD + pos] = gl;
        }
    }
}

// ---------------------------------------------------------------------------
extern "C" void kernel_launch(void* const* d_in, const int* in_sizes, int n_in,
                              void* d_out, int out_size) {
    const float* x      = (const float*)d_in[0];
    const float* qkv_w  = (const float*)d_in[1];
    const float* bn1_g  = (const float*)d_in[2];
    const float* bn1_b  = (const float*)d_in[3];
    const float* bn1_m  = (const float*)d_in[4];
    const float* bn1_v  = (const float*)d_in[5];
    const float* proj_w = (const float*)d_in[6];
    const float* bn2_g  = (const float*)d_in[7];
    const float* bn2_b  = (const float*)d_in[8];
    const float* bn2_m  = (const float*)d_in[9];
    const float* bn2_v  = (const float*)d_in[10];
    const float* ab     = (const float*)d_in[11];
    const int*   idxs   = (const int*)d_in[12];
    float* out = (float*)d_out;

    const int smem_attn = (3 * HD * NQ + NQ * 29 + 2 * NQ) * sizeof(float); // ~174.8KB
    cudaFuncSetAttribute(attn_kernel,
                         cudaFuncAttributeMaxDynamicSharedMemorySize, smem_attn);

    {   // pad x
        int total = B_ * CIN * NPAD;
        pad_x_kernel<<<(total + 255) / 256, 256>>>(x);
    }
    {   // bias gather
        int total = HEADS * NQ * NQ;
        gather_bias_kernel<<<(total + 255) / 256, 256>>>(ab, idxs);
    }
    {   // QKV GEMM + BN1 (tf32 tensor cores)
        dim3 grid(NPAD / 112, (3 * CIN) / 128, B_);
        gemm_tf32<0><<<grid, 256>>>(qkv_w, bn1_g, bn1_b, bn1_m, bn1_v, nullptr);
    }
    {   // attention + gelu + scrambled reshape
        attn_kernel<<<B_ * HEADS, 448, smem_attn>>>();
    }
    {   // proj GEMM + BN2 -> d_out (tf32 tensor cores)
        dim3 grid(NPAD / 112, CIN / 128, B_);
        gemm_tf32<1><<<grid, 256>>>(proj_w, bn2_g, bn2_b, bn2_m, bn2_v, out);
    }
}

// round 5
// speedup vs baseline: 1.8479x; 1.0693x over previous
#include <cuda_runtime.h>
#include <math.h>

// ---------------------------------------------------------------------------
// GlobalMHSAWithPosBias: B=128, C=512, RES=14 (N=196), HEADS=8, hd=64
// Round 5: round-2 state (known pass) + tensor-core attention only.
// attn: 224 threads / 7 warps, reg cap 255 -> spill impossible.
// ---------------------------------------------------------------------------

#define B_    128
#define CIN   512
#define NQ    196
#define NPAD  224          // 4 * 56 = 2 * 112
#define HEADS 8
#define HD    64
#define EPS_  1e-5f

__device__ float g_xp  [(size_t)B_ * CIN * NPAD];        // padded input
__device__ float g_qkv [(size_t)B_ * 3 * CIN * NPAD];    // qkv, BN1 applied
__device__ float g_att [(size_t)B_ * CIN * NPAD];        // gelu(o), scrambled layout
__device__ float g_biasT[HEADS * NQ * NQ];               // bias [h][m][n] (symmetric idx)

// ---------------------------------------------------------------------------
__global__ void pad_x_kernel(const float* __restrict__ x) {
    int i = blockIdx.x * blockDim.x + threadIdx.x;
    const int total = B_ * CIN * NPAD;
    if (i >= total) return;
    int n  = i % NPAD;
    int rc = i / NPAD;
    g_xp[i] = (n < NQ) ? x[(size_t)rc * NQ + n] : 0.f;
}

__global__ void gather_bias_kernel(const float* __restrict__ ab,
                                   const int*   __restrict__ idxs) {
    int i = blockIdx.x * blockDim.x + threadIdx.x;
    const int total = HEADS * NQ * NQ;
    if (i >= total) return;
    int stride = (idxs[1] == 0 && idxs[3] == 0) ? 2 : 1;   // int64 detection
    int h = i / (NQ * NQ);
    int j = i - h * (NQ * NQ);
    g_biasT[i] = ab[h * NQ + idxs[(size_t)j * stride]];
}

// ---------------------------------------------------------------------------
// tf32 helpers
// ---------------------------------------------------------------------------
__device__ __forceinline__ unsigned f2tf32(float f) {
    unsigned u;
    asm("cvt.rna.tf32.f32 %0, %1;" : "=r"(u) : "f"(f));
    return u;
}

__device__ __forceinline__ void mma_tf32(float c[4], const unsigned a[4],
                                         unsigned b0, unsigned b1) {
    asm volatile(
        "mma.sync.aligned.m16n8k8.row.col.f32.tf32.tf32.f32 "
        "{%0,%1,%2,%3}, {%4,%5,%6,%7}, {%8,%9}, {%0,%1,%2,%3};\n"
        : "+f"(c[0]), "+f"(c[1]), "+f"(c[2]), "+f"(c[3])
        : "r"(a[0]), "r"(a[1]), "r"(a[2]), "r"(a[3]), "r"(b0), "r"(b1));
}

// ---------------------------------------------------------------------------
// tf32 tensor-core GEMM + fused BN affine (EXACT round-2 version; passed).
// MODE 0: X=g_xp,  Y=g_qkv (O=1536, ldy=224)   MODE 1: X=g_att, Y=out (O=512, ldy=196)
// BM=128, BN=112, BK=32, 256 threads (8 warps, 4m x 2n), warp tile 32x56.
// ---------------------------------------------------------------------------
#define WPITCH 36
#define XPITCH 120

template <int MODE>
__global__ __launch_bounds__(256)
void gemm_tf32(const float* __restrict__ W,
               const float* __restrict__ gamma, const float* __restrict__ beta,
               const float* __restrict__ mean,  const float* __restrict__ var,
               float* __restrict__ outp) {
    const float* __restrict__ X = (MODE == 0) ? g_xp : g_att;
    float* __restrict__ Y       = (MODE == 0) ? g_qkv : outp;
    const int Ocnt = (MODE == 0) ? 3 * CIN : CIN;
    const int ldy  = (MODE == 0) ? NPAD : NQ;

    __shared__ unsigned Ws[128 * WPITCH];
    __shared__ unsigned Xs[32 * XPITCH];

    const int tid  = threadIdx.x;
    const int lane = tid & 31;
    const int wid  = tid >> 5;
    const int m0w  = (wid & 3) * 32;
    const int n0w  = (wid >> 2) * 56;

    const int b  = blockIdx.z;
    const int o0 = blockIdx.y * 128;
    const int n0 = blockIdx.x * 112;

    const float* __restrict__ Wp = W + (size_t)o0 * CIN;
    const float* __restrict__ Xp = X + (size_t)b * CIN * NPAD + n0;

    float acc[2][7][4];
#pragma unroll
    for (int i = 0; i < 2; i++)
#pragma unroll
        for (int j = 0; j < 7; j++)
#pragma unroll
            for (int k = 0; k < 4; k++) acc[i][j][k] = 0.f;

    const int row = lane >> 2;
    const int col = lane & 3;

    for (int kk = 0; kk < CIN; kk += 32) {
#pragma unroll
        for (int i = tid; i < 1024; i += 256) {
            int r  = i >> 3;
            int c4 = (i & 7) * 4;
            float4 w = *(const float4*)(Wp + (size_t)r * CIN + kk + c4);
            Ws[r * WPITCH + c4 + 0] = f2tf32(w.x);
            Ws[r * WPITCH + c4 + 1] = f2tf32(w.y);
            Ws[r * WPITCH + c4 + 2] = f2tf32(w.z);
            Ws[r * WPITCH + c4 + 3] = f2tf32(w.w);
        }
        for (int i = tid; i < 896; i += 256) {
            int r  = i / 28;
            int c4 = (i % 28) * 4;
            float4 xv = *(const float4*)(Xp + (size_t)(kk + r) * NPAD + c4);
            Xs[r * XPITCH + c4 + 0] = f2tf32(xv.x);
            Xs[r * XPITCH + c4 + 1] = f2tf32(xv.y);
            Xs[r * XPITCH + c4 + 2] = f2tf32(xv.z);
            Xs[r * XPITCH + c4 + 3] = f2tf32(xv.w);
        }
        __syncthreads();

#pragma unroll
        for (int ks = 0; ks < 4; ks++) {
            const int k0 = ks * 8;
            unsigned a[2][4];
#pragma unroll
            for (int mt = 0; mt < 2; mt++) {
                int base = (m0w + mt * 16 + row) * WPITCH + k0 + col;
                a[mt][0] = Ws[base];
                a[mt][1] = Ws[base + 8 * WPITCH];
                a[mt][2] = Ws[base + 4];
                a[mt][3] = Ws[base + 8 * WPITCH + 4];
            }
#pragma unroll
            for (int nt = 0; nt < 7; nt++) {
                int bb = (k0 + col) * XPITCH + n0w + nt * 8 + row;
                unsigned b0 = Xs[bb];
                unsigned b1 = Xs[bb + 4 * XPITCH];
                mma_tf32(acc[0][nt], a[0], b0, b1);
                mma_tf32(acc[1][nt], a[1], b0, b1);
            }
        }
        __syncthreads();
    }

#pragma unroll
    for (int mt = 0; mt < 2; mt++) {
        int o_a = o0 + m0w + mt * 16 + row;
        int o_b = o_a + 8;
        float inv_a = gamma[o_a] * rsqrtf(var[o_a] + EPS_);
        float sh_a  = beta[o_a] - mean[o_a] * inv_a;
        float inv_b = gamma[o_b] * rsqrtf(var[o_b] + EPS_);
        float sh_b  = beta[o_b] - mean[o_b] * inv_b;
        float* ya = Y + ((size_t)b * Ocnt + o_a) * ldy;
        float* yb = Y + ((size_t)b * Ocnt + o_b) * ldy;
#pragma unroll
        for (int nt = 0; nt < 7; nt++) {
            int c0 = n0 + n0w + nt * 8 + col * 2;
            float y0 = acc[mt][nt][0] * inv_a + sh_a;
            float y1 = acc[mt][nt][1] * inv_a + sh_a;
            float y2 = acc[mt][nt][2] * inv_b + sh_b;
            float y3 = acc[mt][nt][3] * inv_b + sh_b;
            if (MODE == 0) {
                *(float2*)(ya + c0) = make_float2(y0, y1);
                *(float2*)(yb + c0) = make_float2(y2, y3);
            } else {
                if (c0 < NQ)     { ya[c0]     = y0; yb[c0]     = y2; }
                if (c0 + 1 < NQ) { ya[c0 + 1] = y1; yb[c0 + 1] = y3; }
            }
        }
    }
}

// ---------------------------------------------------------------------------
// Tensor-core attention. Block = (b, h, half): 224 threads = 7 warps, each
// warp owns one 16-row n-tile of its 112-row half. Q (half) pitch 120, K
// pitch 232, V^T pitch 72, warp-private P [16][36]. All fragment LDS
// conflict-free. Exp-safe softmax (scores O(1)); pad columns (m>=196) give
// p=0; dead rows (n>=196) clamp bias row and never store.
// Reg budget: ~100 live, cap 255 at 224 threads -> no spill possible.
// ---------------------------------------------------------------------------
#define QPITCH 120
#define KPITCH 232
#define VPITCH 72
#define PPITCH 36
#define QS_SZ  (64 * QPITCH)
#define KS_SZ  (64 * KPITCH)
#define VS_SZ  (224 * VPITCH)
#define PT_SZ  (16 * PPITCH)

__global__ __launch_bounds__(224)
void attn_kernel() {
    extern __shared__ unsigned sm[];
    unsigned* Qs = sm;                          // [d][ml]  half rows
    unsigned* Ks = sm + QS_SZ;                  // [d][m]
    unsigned* Vs = sm + QS_SZ + KS_SZ;          // [m][d]
    unsigned* Pt = sm + QS_SZ + KS_SZ + VS_SZ;  // [warp][16][36]

    const int tid  = threadIdx.x;
    const int lane = tid & 31;
    const int w    = tid >> 5;          // 0..6
    const int row  = lane >> 2;         // 0..7
    const int col  = lane & 3;          // 0..3
    const int bid  = blockIdx.x;
    const int half = bid & 1;
    const int h    = (bid >> 1) & 7;
    const int b    = bid >> 4;
    const int nblk = half * 112;
    const int n0   = nblk + w * 16;     // global row base for this warp

    const size_t base = ((size_t)b * 3 * CIN + h * HD) * NPAD;
    const float* __restrict__ Qg = g_qkv + base;
    const float* __restrict__ Kg = g_qkv + base + (size_t)CIN * NPAD;
    const float* __restrict__ Vg = g_qkv + base + (size_t)2 * CIN * NPAD;

    // stage K [d][m], V^T [m][d]: thread handles column m = tid for all d
#pragma unroll 4
    for (int d = 0; d < HD; d++) {
        Ks[d * KPITCH + tid] = f2tf32(Kg[(size_t)d * NPAD + tid]);
        Vs[tid * VPITCH + d] = f2tf32(Vg[(size_t)d * NPAD + tid]);
    }
    // stage Q for this half: 64 x 112
    for (int i = tid; i < HD * 112; i += 224) {
        int d = i / 112, ml = i - d * 112;
        Qs[d * QPITCH + ml] = f2tf32(Qg[(size_t)d * NPAD + nblk + ml]);
    }
    __syncthreads();

    const float* __restrict__ bptr = g_biasT + (size_t)h * NQ * NQ;
    unsigned* ptw = Pt + w * PT_SZ;
    const int nb_lo = min(n0 + row, NQ - 1);       // bias row clamp (dead rows)
    const int nb_hi = min(n0 + row + 8, NQ - 1);

    float o[8][4];
#pragma unroll
    for (int i = 0; i < 8; i++)
#pragma unroll
        for (int j = 0; j < 4; j++) o[i][j] = 0.f;
    float ll = 0.f, lh = 0.f;

    for (int mc = 0; mc < 7; mc++) {
        const int m0 = mc * 32;

        // ---- S = Q^T K for columns [m0, m0+32): 4 interleaved mma chains ----
        float c[4][4];
#pragma unroll
        for (int s = 0; s < 4; s++)
#pragma unroll
            for (int j = 0; j < 4; j++) c[s][j] = 0.f;

#pragma unroll
        for (int k8 = 0; k8 < 8; k8++) {
            const int d8 = k8 * 8 + col;
            unsigned a[4];
            a[0] = Qs[d8 * QPITCH + w * 16 + row];
            a[1] = Qs[d8 * QPITCH + w * 16 + row + 8];
            a[2] = Qs[(d8 + 4) * QPITCH + w * 16 + row];
            a[3] = Qs[(d8 + 4) * QPITCH + w * 16 + row + 8];
#pragma unroll
            for (int s = 0; s < 4; s++) {
                const int bb = d8 * KPITCH + m0 + s * 8 + row;
                mma_tf32(c[s], a, Ks[bb], Ks[bb + 4 * KPITCH]);
            }
        }

        // exp + bias -> Pt
#pragma unroll
        for (int s = 0; s < 4; s++) {
            const int m_b = m0 + s * 8 + 2 * col;      // even; pair in/out together
            float p0 = 0.f, p1 = 0.f, p2 = 0.f, p3 = 0.f;
            if (m_b < NQ) {
                float2 blo = *(const float2*)(bptr + (size_t)nb_lo * NQ + m_b);
                float2 bhi = *(const float2*)(bptr + (size_t)nb_hi * NQ + m_b);
                p0 = __expf(c[s][0] * 0.125f + blo.x);
                p1 = __expf(c[s][1] * 0.125f + blo.y);
                p2 = __expf(c[s][2] * 0.125f + bhi.x);
                p3 = __expf(c[s][3] * 0.125f + bhi.y);
            }
            ll += p0 + p1;
            lh += p2 + p3;
            int pc = s * 8 + 2 * col;
            ptw[row * PPITCH + pc]           = f2tf32(p0);
            ptw[row * PPITCH + pc + 1]       = f2tf32(p1);
            ptw[(row + 8) * PPITCH + pc]     = f2tf32(p2);
            ptw[(row + 8) * PPITCH + pc + 1] = f2tf32(p3);
        }
        __syncwarp();

        // ---- O += P V^T over this m-chunk ----
#pragma unroll
        for (int k4 = 0; k4 < 4; k4++) {
            const int k0 = k4 * 8;
            unsigned a[4];
            a[0] = ptw[row * PPITCH + k0 + col];
            a[1] = ptw[(row + 8) * PPITCH + k0 + col];
            a[2] = ptw[row * PPITCH + k0 + col + 4];
            a[3] = ptw[(row + 8) * PPITCH + k0 + col + 4];
#pragma unroll
            for (int nc = 0; nc < 8; nc++) {
                int bb = (m0 + k0 + col) * VPITCH + nc * 8 + row;
                mma_tf32(o[nc], a, Vs[bb], Vs[bb + 4 * VPITCH]);
            }
        }
        __syncwarp();
    }

    // row sums across the quad
    ll += __shfl_xor_sync(0xffffffffu, ll, 1);
    ll += __shfl_xor_sync(0xffffffffu, ll, 2);
    lh += __shfl_xor_sync(0xffffffffu, lh, 1);
    lh += __shfl_xor_sync(0xffffffffu, lh, 2);
    const float linv_lo = 1.f / ll;
    const float linv_hi = 1.f / lh;

    const int n_lo = n0 + row;
    const int n_hi = n0 + row + 8;
#pragma unroll
    for (int nc = 0; nc < 8; nc++) {
        int d0 = nc * 8 + 2 * col;
#pragma unroll
        for (int j = 0; j < 2; j++) {
            int d = d0 + j;
            if (n_lo < NQ) {
                float v = o[nc][j] * linv_lo;
                float gl = 0.5f * v * (1.f + erff(v * 0.70710678118654752f));
                int flat = h * (NQ * HD) + n_lo * HD + d;
                int cc   = flat / NQ;
                int pos  = flat - cc * NQ;
                g_att[((size_t)b * CIN + cc) * NPAD + pos] = gl;
            }
            if (n_hi < NQ) {
                float v = o[nc][j + 2] * linv_hi;
                float gl = 0.5f * v * (1.f + erff(v * 0.70710678118654752f));
                int flat = h * (NQ * HD) + n_hi * HD + d;
                int cc   = flat / NQ;
                int pos  = flat - cc * NQ;
                g_att[((size_t)b * CIN + cc) * NPAD + pos] = gl;
            }
        }
    }
}

// ---------------------------------------------------------------------------
extern "C" void kernel_launch(void* const* d_in, const int* in_sizes, int n_in,
                              void* d_out, int out_size) {
    const float* x      = (const float*)d_in[0];
    const float* qkv_w  = (const float*)d_in[1];
    const float* bn1_g  = (const float*)d_in[2];
    const float* bn1_b  = (const float*)d_in[3];
    const float* bn1_m  = (const float*)d_in[4];
    const float* bn1_v  = (const float*)d_in[5];
    const float* proj_w = (const float*)d_in[6];
    const float* bn2_g  = (const float*)d_in[7];
    const float* bn2_b  = (const float*)d_in[8];
    const float* bn2_m  = (const float*)d_in[9];
    const float* bn2_v  = (const float*)d_in[10];
    const float* ab     = (const float*)d_in[11];
    const int*   idxs   = (const int*)d_in[12];
    float* out = (float*)d_out;

    const int smem_attn = (QS_SZ + KS_SZ + VS_SZ + 7 * PT_SZ) * 4;  // 170752 B
    cudaFuncSetAttribute(attn_kernel,
                         cudaFuncAttributeMaxDynamicSharedMemorySize, smem_attn);

    {   // pad x
        int total = B_ * CIN * NPAD;
        pad_x_kernel<<<(total + 255) / 256, 256>>>(x);
    }
    {   // bias gather
        int total = HEADS * NQ * NQ;
        gather_bias_kernel<<<(total + 255) / 256, 256>>>(ab, idxs);
    }
    {   // QKV GEMM + BN1 (tf32 tensor cores)
        dim3 grid(NPAD / 112, (3 * CIN) / 128, B_);
        gemm_tf32<0><<<grid, 256>>>(qkv_w, bn1_g, bn1_b, bn1_m, bn1_v, nullptr);
    }
    {   // attention + gelu + scrambled reshape (tensor cores)
        attn_kernel<<<B_ * HEADS * 2, 224, smem_attn>>>();
    }
    {   // proj GEMM + BN2 -> d_out
        dim3 grid(NPAD / 112, CIN / 128, B_);
        gemm_tf32<1><<<grid, 256>>>(proj_w, bn2_g, bn2_b, bn2_m, bn2_v, out);
    }
}

// round 6
// speedup vs baseline: 2.4864x; 1.3455x over previous
#include <cuda_runtime.h>
#include <math.h>

// ---------------------------------------------------------------------------
// GlobalMHSAWithPosBias: B=128, C=512, RES=14 (N=196), HEADS=8, hd=64
// Round 6: attn 448thr/14warps with register-Q; pad_x folded into QKV GEMM.
// NOTE: never pass __device__ symbols (g_att etc.) from host code — that was
// the rounds-3/4 failure. All scratch selection happens device-side.
// ---------------------------------------------------------------------------

#define B_    128
#define CIN   512
#define NQ    196
#define NPAD  224          // 4 * 56 = 2 * 112
#define HEADS 8
#define HD    64
#define EPS_  1e-5f

__device__ float g_qkv [(size_t)B_ * 3 * CIN * NPAD];    // qkv, BN1 applied
__device__ float g_att [(size_t)B_ * CIN * NPAD];        // gelu(o), scrambled layout
__device__ float g_biasT[HEADS * NQ * NQ];               // bias [h][m][n] (symmetric idx)

// ---------------------------------------------------------------------------
__global__ void gather_bias_kernel(const float* __restrict__ ab,
                                   const int*   __restrict__ idxs) {
    int i = blockIdx.x * blockDim.x + threadIdx.x;
    const int total = HEADS * NQ * NQ;
    if (i >= total) return;
    int stride = (idxs[1] == 0 && idxs[3] == 0) ? 2 : 1;   // int64 detection
    int h = i / (NQ * NQ);
    int j = i - h * (NQ * NQ);
    g_biasT[i] = ab[h * NQ + idxs[(size_t)j * stride]];
}

// ---------------------------------------------------------------------------
// tf32 helpers
// ---------------------------------------------------------------------------
__device__ __forceinline__ unsigned f2tf32(float f) {
    unsigned u;
    asm("cvt.rna.tf32.f32 %0, %1;" : "=r"(u) : "f"(f));
    return u;
}

__device__ __forceinline__ void mma_tf32(float c[4], const unsigned a[4],
                                         unsigned b0, unsigned b1) {
    asm volatile(
        "mma.sync.aligned.m16n8k8.row.col.f32.tf32.tf32.f32 "
        "{%0,%1,%2,%3}, {%4,%5,%6,%7}, {%8,%9}, {%0,%1,%2,%3};\n"
        : "+f"(c[0]), "+f"(c[1]), "+f"(c[2]), "+f"(c[3])
        : "r"(a[0]), "r"(a[1]), "r"(a[2]), "r"(a[3]), "r"(b0), "r"(b1));
}

// ---------------------------------------------------------------------------
// tf32 tensor-core GEMM + fused BN affine.
// MODE 0: X = Xg (harness x pointer, [b][c][196], guarded read, pad=0),
//         Y = g_qkv (ldy=224)
// MODE 1: X = g_att (device-side symbol, [b][c][224]), Y = outp (ldy=196)
// BM=128, BN=112, BK=32, 256 threads (8 warps, 4m x 2n), warp tile 32x56.
// ---------------------------------------------------------------------------
#define WPITCH 36
#define XPITCH 120

template <int MODE>
__global__ __launch_bounds__(256)
void gemm_tf32(const float* __restrict__ Xg,
               const float* __restrict__ W,
               const float* __restrict__ gamma, const float* __restrict__ beta,
               const float* __restrict__ mean,  const float* __restrict__ var,
               float* __restrict__ outp) {
    const float* __restrict__ X = (MODE == 0) ? Xg : g_att;   // device-side!
    float* __restrict__ Y       = (MODE == 0) ? g_qkv : outp;
    const int Ocnt = (MODE == 0) ? 3 * CIN : CIN;
    const int ldy  = (MODE == 0) ? NPAD : NQ;
    const int ldx  = (MODE == 0) ? NQ : NPAD;

    __shared__ unsigned Ws[128 * WPITCH];
    __shared__ unsigned Xs[32 * XPITCH];

    const int tid  = threadIdx.x;
    const int lane = tid & 31;
    const int wid  = tid >> 5;
    const int m0w  = (wid & 3) * 32;
    const int n0w  = (wid >> 2) * 56;

    const int b  = blockIdx.z;
    const int o0 = blockIdx.y * 128;
    const int n0 = blockIdx.x * 112;

    const float* __restrict__ Wp = W + (size_t)o0 * CIN;
    const float* __restrict__ Xp = X + (size_t)b * CIN * ldx + n0;

    float acc[2][7][4];
#pragma unroll
    for (int i = 0; i < 2; i++)
#pragma unroll
        for (int j = 0; j < 7; j++)
#pragma unroll
            for (int k = 0; k < 4; k++) acc[i][j][k] = 0.f;

    const int row = lane >> 2;
    const int col = lane & 3;

    for (int kk = 0; kk < CIN; kk += 32) {
#pragma unroll
        for (int i = tid; i < 1024; i += 256) {
            int r  = i >> 3;
            int c4 = (i & 7) * 4;
            float4 w = *(const float4*)(Wp + (size_t)r * CIN + kk + c4);
            Ws[r * WPITCH + c4 + 0] = f2tf32(w.x);
            Ws[r * WPITCH + c4 + 1] = f2tf32(w.y);
            Ws[r * WPITCH + c4 + 2] = f2tf32(w.z);
            Ws[r * WPITCH + c4 + 3] = f2tf32(w.w);
        }
        for (int i = tid; i < 896; i += 256) {
            int r  = i / 28;
            int c4 = (i % 28) * 4;
            float4 xv = make_float4(0.f, 0.f, 0.f, 0.f);
            if (MODE == 1 || (n0 + c4) < NQ)
                xv = *(const float4*)(Xp + (size_t)(kk + r) * ldx + c4);
            Xs[r * XPITCH + c4 + 0] = f2tf32(xv.x);
            Xs[r * XPITCH + c4 + 1] = f2tf32(xv.y);
            Xs[r * XPITCH + c4 + 2] = f2tf32(xv.z);
            Xs[r * XPITCH + c4 + 3] = f2tf32(xv.w);
        }
        __syncthreads();

#pragma unroll
        for (int ks = 0; ks < 4; ks++) {
            const int k0 = ks * 8;
            unsigned a[2][4];
#pragma unroll
            for (int mt = 0; mt < 2; mt++) {
                int base = (m0w + mt * 16 + row) * WPITCH + k0 + col;
                a[mt][0] = Ws[base];
                a[mt][1] = Ws[base + 8 * WPITCH];
                a[mt][2] = Ws[base + 4];
                a[mt][3] = Ws[base + 8 * WPITCH + 4];
            }
#pragma unroll
            for (int nt = 0; nt < 7; nt++) {
                int bb = (k0 + col) * XPITCH + n0w + nt * 8 + row;
                unsigned b0 = Xs[bb];
                unsigned b1 = Xs[bb + 4 * XPITCH];
                mma_tf32(acc[0][nt], a[0], b0, b1);
                mma_tf32(acc[1][nt], a[1], b0, b1);
            }
        }
        __syncthreads();
    }

#pragma unroll
    for (int mt = 0; mt < 2; mt++) {
        int o_a = o0 + m0w + mt * 16 + row;
        int o_b = o_a + 8;
        float inv_a = gamma[o_a] * rsqrtf(var[o_a] + EPS_);
        float sh_a  = beta[o_a] - mean[o_a] * inv_a;
        float inv_b = gamma[o_b] * rsqrtf(var[o_b] + EPS_);
        float sh_b  = beta[o_b] - mean[o_b] * inv_b;
        float* ya = Y + ((size_t)b * Ocnt + o_a) * ldy;
        float* yb = Y + ((size_t)b * Ocnt + o_b) * ldy;
#pragma unroll
        for (int nt = 0; nt < 7; nt++) {
            int c0 = n0 + n0w + nt * 8 + col * 2;
            float y0 = acc[mt][nt][0] * inv_a + sh_a;
            float y1 = acc[mt][nt][1] * inv_a + sh_a;
            float y2 = acc[mt][nt][2] * inv_b + sh_b;
            float y3 = acc[mt][nt][3] * inv_b + sh_b;
            if (MODE == 0) {
                *(float2*)(ya + c0) = make_float2(y0, y1);
                *(float2*)(yb + c0) = make_float2(y2, y3);
            } else {
                if (c0 < NQ)     { ya[c0]     = y0; yb[c0]     = y2; }
                if (c0 + 1 < NQ) { ya[c0 + 1] = y1; yb[c0 + 1] = y3; }
            }
        }
    }
}

// ---------------------------------------------------------------------------
// Tensor-core attention. One block per (b,h): 448 threads = 14 warps, warp w
// owns n-rows [16w, 16w+16). Q A-fragments live in registers (loaded once
// from gmem). K smem [d][m] pitch 232, V^T smem [m][d] pitch 72, P in
// warp-private smem [16][36]. Exp-safe softmax; pad columns (m>=196) give
// p=0; dead rows (n>=196) clamp bias row, never store.
// regs ~110 (< 144 cap at 448 thr).
// ---------------------------------------------------------------------------
#define KPITCH 232
#define VPITCH 72
#define PPITCH 36
#define KS_SZ  (64 * KPITCH)
#define VS_SZ  (224 * VPITCH)
#define PT_SZ  (16 * PPITCH)

__global__ __launch_bounds__(448)
void attn_kernel() {
    extern __shared__ unsigned sm[];
    unsigned* Ks = sm;                  // [d][m]
    unsigned* Vs = sm + KS_SZ;          // [m][d]
    unsigned* Pt = sm + KS_SZ + VS_SZ;  // [warp][16][36]

    const int tid  = threadIdx.x;
    const int lane = tid & 31;
    const int w    = tid >> 5;          // 0..13
    const int row  = lane >> 2;         // 0..7
    const int col  = lane & 3;          // 0..3
    const int b    = blockIdx.x >> 3;
    const int h    = blockIdx.x & 7;
    const int n0   = w * 16;

    const size_t base = ((size_t)b * 3 * CIN + h * HD) * NPAD;
    const float* __restrict__ Qg = g_qkv + base;
    const float* __restrict__ Kg = g_qkv + base + (size_t)CIN * NPAD;
    const float* __restrict__ Vg = g_qkv + base + (size_t)2 * CIN * NPAD;

    // stage K [d][m] and V^T [m][d]
    for (int i = tid; i < HD * NPAD; i += 448) {
        int d = i / NPAD, m = i - d * NPAD;
        Ks[d * KPITCH + m] = f2tf32(Kg[i]);
        Vs[m * VPITCH + d] = f2tf32(Vg[i]);
    }

    // preload Q A-frags from gmem: aQ[k8] covers d = 8*k8 .. 8*k8+7
    unsigned aQ[8][4];
#pragma unroll
    for (int k8 = 0; k8 < 8; k8++) {
        int d0 = k8 * 8;
        aQ[k8][0] = f2tf32(Qg[(d0 + col) * NPAD + n0 + row]);
        aQ[k8][1] = f2tf32(Qg[(d0 + col) * NPAD + n0 + row + 8]);
        aQ[k8][2] = f2tf32(Qg[(d0 + col + 4) * NPAD + n0 + row]);
        aQ[k8][3] = f2tf32(Qg[(d0 + col + 4) * NPAD + n0 + row + 8]);
    }
    __syncthreads();

    const float* __restrict__ bptr = g_biasT + (size_t)h * NQ * NQ;
    unsigned* ptw = Pt + w * PT_SZ;
    const int nb_lo = min(n0 + row, NQ - 1);       // bias row clamp (dead rows)
    const int nb_hi = min(n0 + row + 8, NQ - 1);

    float o[8][4];
#pragma unroll
    for (int i = 0; i < 8; i++)
#pragma unroll
        for (int j = 0; j < 4; j++) o[i][j] = 0.f;
    float ll = 0.f, lh = 0.f;

    for (int mc = 0; mc < 7; mc++) {
        const int m0 = mc * 32;

        // ---- S = Q^T K for columns [m0, m0+32): 4 interleaved mma chains ----
        float c[4][4];
#pragma unroll
        for (int s = 0; s < 4; s++)
#pragma unroll
            for (int j = 0; j < 4; j++) c[s][j] = 0.f;

#pragma unroll
        for (int k8 = 0; k8 < 8; k8++) {
            const int d8 = k8 * 8 + col;
#pragma unroll
            for (int s = 0; s < 4; s++) {
                const int bb = d8 * KPITCH + m0 + s * 8 + row;
                mma_tf32(c[s], aQ[k8], Ks[bb], Ks[bb + 4 * KPITCH]);
            }
        }

        // exp + bias -> Pt
#pragma unroll
        for (int s = 0; s < 4; s++) {
            const int m_b = m0 + s * 8 + 2 * col;      // even; pair in/out together
            float p0 = 0.f, p1 = 0.f, p2 = 0.f, p3 = 0.f;
            if (m_b < NQ) {
                float2 blo = *(const float2*)(bptr + (size_t)nb_lo * NQ + m_b);
                float2 bhi = *(const float2*)(bptr + (size_t)nb_hi * NQ + m_b);
                p0 = __expf(c[s][0] * 0.125f + blo.x);
                p1 = __expf(c[s][1] * 0.125f + blo.y);
                p2 = __expf(c[s][2] * 0.125f + bhi.x);
                p3 = __expf(c[s][3] * 0.125f + bhi.y);
            }
            ll += p0 + p1;
            lh += p2 + p3;
            int pc = s * 8 + 2 * col;
            ptw[row * PPITCH + pc]           = f2tf32(p0);
            ptw[row * PPITCH + pc + 1]       = f2tf32(p1);
            ptw[(row + 8) * PPITCH + pc]     = f2tf32(p2);
            ptw[(row + 8) * PPITCH + pc + 1] = f2tf32(p3);
        }
        __syncwarp();

        // ---- O += P V^T over this m-chunk ----
#pragma unroll
        for (int k4 = 0; k4 < 4; k4++) {
            const int k0 = k4 * 8;
            unsigned a[4];
            a[0] = ptw[row * PPITCH + k0 + col];
            a[1] = ptw[(row + 8) * PPITCH + k0 + col];
            a[2] = ptw[row * PPITCH + k0 + col + 4];
            a[3] = ptw[(row + 8) * PPITCH + k0 + col + 4];
#pragma unroll
            for (int nc = 0; nc < 8; nc++) {
                int bb = (m0 + k0 + col) * VPITCH + nc * 8 + row;
                mma_tf32(o[nc], a, Vs[bb], Vs[bb + 4 * VPITCH]);
            }
        }
        __syncwarp();
    }

    // row sums across the quad
    ll += __shfl_xor_sync(0xffffffffu, ll, 1);
    ll += __shfl_xor_sync(0xffffffffu, ll, 2);
    lh += __shfl_xor_sync(0xffffffffu, lh, 1);
    lh += __shfl_xor_sync(0xffffffffu, lh, 2);
    const float linv_lo = 1.f / ll;
    const float linv_hi = 1.f / lh;

    const int n_lo = n0 + row;
    const int n_hi = n0 + row + 8;
#pragma unroll
    for (int nc = 0; nc < 8; nc++) {
        int d0 = nc * 8 + 2 * col;
#pragma unroll
        for (int j = 0; j < 2; j++) {
            int d = d0 + j;
            if (n_lo < NQ) {
                float v = o[nc][j] * linv_lo;
                float gl = 0.5f * v * (1.f + erff(v * 0.70710678118654752f));
                int flat = h * (NQ * HD) + n_lo * HD + d;
                int cc   = flat / NQ;
                int pos  = flat - cc * NQ;
                g_att[((size_t)b * CIN + cc) * NPAD + pos] = gl;
            }
            if (n_hi < NQ) {
                float v = o[nc][j + 2] * linv_hi;
                float gl = 0.5f * v * (1.f + erff(v * 0.70710678118654752f));
                int flat = h * (NQ * HD) + n_hi * HD + d;
                int cc   = flat / NQ;
                int pos  = flat - cc * NQ;
                g_att[((size_t)b * CIN + cc) * NPAD + pos] = gl;
            }
        }
    }
}

// ---------------------------------------------------------------------------
extern "C" void kernel_launch(void* const* d_in, const int* in_sizes, int n_in,
                              void* d_out, int out_size) {
    const float* x      = (const float*)d_in[0];
    const float* qkv_w  = (const float*)d_in[1];
    const float* bn1_g  = (const float*)d_in[2];
    const float* bn1_b  = (const float*)d_in[3];
    const float* bn1_m  = (const float*)d_in[4];
    const float* bn1_v  = (const float*)d_in[5];
    const float* proj_w = (const float*)d_in[6];
    const float* bn2_g  = (const float*)d_in[7];
    const float* bn2_b  = (const float*)d_in[8];
    const float* bn2_m  = (const float*)d_in[9];
    const float* bn2_v  = (const float*)d_in[10];
    const float* ab     = (const float*)d_in[11];
    const int*   idxs   = (const int*)d_in[12];
    float* out = (float*)d_out;

    const int smem_attn = (KS_SZ + VS_SZ + 14 * PT_SZ) * 4;   // 156160 B
    cudaFuncSetAttribute(attn_kernel,
                         cudaFuncAttributeMaxDynamicSharedMemorySize, smem_attn);

    {   // bias gather
        int total = HEADS * NQ * NQ;
        gather_bias_kernel<<<(total + 255) / 256, 256>>>(ab, idxs);
    }
    {   // QKV GEMM + BN1 (reads x directly with pad guard)
        dim3 grid(NPAD / 112, (3 * CIN) / 128, B_);
        gemm_tf32<0><<<grid, 256>>>(x, qkv_w, bn1_g, bn1_b, bn1_m, bn1_v, nullptr);
    }
    {   // attention + gelu + scrambled reshape (tensor cores)
        attn_kernel<<<B_ * HEADS, 448, smem_attn>>>();
    }
    {   // proj GEMM + BN2 -> d_out (X = g_att selected device-side)
        dim3 grid(NPAD / 112, CIN / 128, B_);
        gemm_tf32<1><<<grid, 256>>>(nullptr, proj_w, bn2_g, bn2_b, bn2_m, bn2_v, out);
    }
}

// round 7
// speedup vs baseline: 3.1967x; 1.2857x over previous
#include <cuda_runtime.h>
#include <math.h>

// ---------------------------------------------------------------------------
// GlobalMHSAWithPosBias: B=128, C=512, RES=14 (N=196), HEADS=8, hd=64
// Round 7: all GEMM operands pre-converted to tf32 bits in gmem; GEMMs use
// cp.async 2-stage double buffering. Attention unchanged from round 6.
// NOTE: never pass __device__ symbols from host code (rounds-3/4 bug);
// all scratch selection happens device-side.
// ---------------------------------------------------------------------------

#define B_    128
#define CIN   512
#define NQ    196
#define NPAD  224          // 4 * 56 = 2 * 112
#define HEADS 8
#define HD    64
#define EPS_  1e-5f

__device__ unsigned g_xtf [(size_t)B_ * CIN * NPAD];        // x, tf32, padded (BSS 0)
__device__ unsigned g_wtf [(size_t)(3 * CIN + CIN) * CIN];  // qkv_w ++ proj_w, tf32
__device__ unsigned g_qkv [(size_t)B_ * 3 * CIN * NPAD];    // qkv post-BN1, tf32 bits
__device__ unsigned g_att [(size_t)B_ * CIN * NPAD];        // gelu(o), tf32, scrambled
__device__ float    g_biasT[HEADS * NQ * NQ];               // bias [h][m][n]

// ---------------------------------------------------------------------------
// tf32 + cp.async helpers
// ---------------------------------------------------------------------------
__device__ __forceinline__ unsigned f2tf32(float f) {
    unsigned u;
    asm("cvt.rna.tf32.f32 %0, %1;" : "=r"(u) : "f"(f));
    return u;
}

__device__ __forceinline__ void mma_tf32(float c[4], const unsigned a[4],
                                         unsigned b0, unsigned b1) {
    asm volatile(
        "mma.sync.aligned.m16n8k8.row.col.f32.tf32.tf32.f32 "
        "{%0,%1,%2,%3}, {%4,%5,%6,%7}, {%8,%9}, {%0,%1,%2,%3};\n"
        : "+f"(c[0]), "+f"(c[1]), "+f"(c[2]), "+f"(c[3])
        : "r"(a[0]), "r"(a[1]), "r"(a[2]), "r"(a[3]), "r"(b0), "r"(b1));
}

__device__ __forceinline__ void cp16(unsigned* dst, const unsigned* src) {
    unsigned s = (unsigned)__cvta_generic_to_shared(dst);
    asm volatile("cp.async.cg.shared.global [%0], [%1], 16;" :: "r"(s), "l"(src));
}
__device__ __forceinline__ void cp_commit() {
    asm volatile("cp.async.commit_group;");
}
template <int N>
__device__ __forceinline__ void cp_wait() {
    asm volatile("cp.async.wait_group %0;" :: "n"(N));
}

// ---------------------------------------------------------------------------
// prologue converters
// ---------------------------------------------------------------------------
__global__ void cvt_w_kernel(const float* __restrict__ qkv_w,
                             const float* __restrict__ proj_w) {
    int i = blockIdx.x * blockDim.x + threadIdx.x;
    const int n1 = 3 * CIN * CIN, total = n1 + CIN * CIN;
    if (i >= total) return;
    float v = (i < n1) ? qkv_w[i] : proj_w[i - n1];
    g_wtf[i] = f2tf32(v);
}

__global__ void pad_cvt_x_kernel(const float* __restrict__ x) {
    int i = blockIdx.x * blockDim.x + threadIdx.x;
    const int total = B_ * CIN * NQ;
    if (i >= total) return;
    int n  = i % NQ;
    int rc = i / NQ;
    g_xtf[(size_t)rc * NPAD + n] = f2tf32(x[i]);   // pad cols stay 0 (BSS)
}

__global__ void gather_bias_kernel(const float* __restrict__ ab,
                                   const int*   __restrict__ idxs) {
    int i = blockIdx.x * blockDim.x + threadIdx.x;
    const int total = HEADS * NQ * NQ;
    if (i >= total) return;
    int stride = (idxs[1] == 0 && idxs[3] == 0) ? 2 : 1;   // int64 detection
    int h = i / (NQ * NQ);
    int j = i - h * (NQ * NQ);
    g_biasT[i] = ab[h * NQ + idxs[(size_t)j * stride]];
}

// ---------------------------------------------------------------------------
// tf32 tensor-core GEMM + fused BN affine, cp.async 2-stage pipeline.
// All operands are pre-converted tf32 bits in gmem.
// MODE 0: X=g_xtf, W=g_wtf,            Y=g_qkv (tf32 bits, ldy=224)
// MODE 1: X=g_att, W=g_wtf+1536*512,   Y=outp  (f32, ldy=196, guarded)
// BM=128, BN=112, BK=32, 256 threads (8 warps, 4m x 2n), warp tile 32x56.
// ---------------------------------------------------------------------------
#define WPITCH 36
#define XPITCH 120
#define WS_TILE (128 * WPITCH)
#define XS_TILE (32 * XPITCH)

template <int MODE>
__global__ __launch_bounds__(256)
void gemm_tf32(const float* __restrict__ gamma, const float* __restrict__ beta,
               const float* __restrict__ mean,  const float* __restrict__ var,
               float* __restrict__ outp) {
    extern __shared__ unsigned smg[];
    unsigned* Ws = smg;                 // 2 stages
    unsigned* Xs = smg + 2 * WS_TILE;   // 2 stages

    const unsigned* __restrict__ X  = (MODE == 0) ? g_xtf : g_att;
    const unsigned* __restrict__ Wt = (MODE == 0) ? g_wtf : (g_wtf + 3 * CIN * CIN);
    const int Ocnt = (MODE == 0) ? 3 * CIN : CIN;
    const int ldy  = (MODE == 0) ? NPAD : NQ;

    const int tid  = threadIdx.x;
    const int lane = tid & 31;
    const int wid  = tid >> 5;
    const int m0w  = (wid & 3) * 32;
    const int n0w  = (wid >> 2) * 56;

    const int b  = blockIdx.z;
    const int o0 = blockIdx.y * 128;
    const int n0 = blockIdx.x * 112;

    const unsigned* __restrict__ Wp = Wt + (size_t)o0 * CIN;
    const unsigned* __restrict__ Xp = X + (size_t)b * CIN * NPAD + n0;

    float acc[2][7][4];
#pragma unroll
    for (int i = 0; i < 2; i++)
#pragma unroll
        for (int j = 0; j < 7; j++)
#pragma unroll
            for (int k = 0; k < 4; k++) acc[i][j][k] = 0.f;

    const int row = lane >> 2;
    const int col = lane & 3;

    auto load_tiles = [&](int kk, int st) {
        unsigned* ws = Ws + st * WS_TILE;
        unsigned* xs = Xs + st * XS_TILE;
#pragma unroll
        for (int i = tid; i < 1024; i += 256) {       // W: 128 x 32
            int r = i >> 3, c4 = (i & 7) * 4;
            cp16(ws + r * WPITCH + c4, Wp + (size_t)r * CIN + kk + c4);
        }
#pragma unroll
        for (int i = tid; i < 896; i += 256) {        // X: 32 x 112
            int r = i / 28, c4 = (i % 28) * 4;
            cp16(xs + r * XPITCH + c4, Xp + (size_t)(kk + r) * NPAD + c4);
        }
        cp_commit();
    };

    load_tiles(0, 0);

    for (int it = 0; it < 16; ++it) {
        const int cur = it & 1;
        if (it + 1 < 16) {
            load_tiles((it + 1) * 32, (it + 1) & 1);
            cp_wait<1>();
        } else {
            cp_wait<0>();
        }
        __syncthreads();

        const unsigned* ws = Ws + cur * WS_TILE;
        const unsigned* xs = Xs + cur * XS_TILE;
#pragma unroll
        for (int ks = 0; ks < 4; ks++) {
            const int k0 = ks * 8;
            unsigned a[2][4];
#pragma unroll
            for (int mt = 0; mt < 2; mt++) {
                int base = (m0w + mt * 16 + row) * WPITCH + k0 + col;
                a[mt][0] = ws[base];
                a[mt][1] = ws[base + 8 * WPITCH];
                a[mt][2] = ws[base + 4];
                a[mt][3] = ws[base + 8 * WPITCH + 4];
            }
#pragma unroll
            for (int nt = 0; nt < 7; nt++) {
                int bb = (k0 + col) * XPITCH + n0w + nt * 8 + row;
                unsigned b0 = xs[bb];
                unsigned b1 = xs[bb + 4 * XPITCH];
                mma_tf32(acc[0][nt], a[0], b0, b1);
                mma_tf32(acc[1][nt], a[1], b0, b1);
            }
        }
        __syncthreads();
    }

    // epilogue: BN affine + store
#pragma unroll
    for (int mt = 0; mt < 2; mt++) {
        int o_a = o0 + m0w + mt * 16 + row;
        int o_b = o_a + 8;
        float inv_a = gamma[o_a] * rsqrtf(var[o_a] + EPS_);
        float sh_a  = beta[o_a] - mean[o_a] * inv_a;
        float inv_b = gamma[o_b] * rsqrtf(var[o_b] + EPS_);
        float sh_b  = beta[o_b] - mean[o_b] * inv_b;
#pragma unroll
        for (int nt = 0; nt < 7; nt++) {
            int c0 = n0 + n0w + nt * 8 + col * 2;
            float y0 = acc[mt][nt][0] * inv_a + sh_a;
            float y1 = acc[mt][nt][1] * inv_a + sh_a;
            float y2 = acc[mt][nt][2] * inv_b + sh_b;
            float y3 = acc[mt][nt][3] * inv_b + sh_b;
            if (MODE == 0) {
                unsigned* ya = g_qkv + ((size_t)b * Ocnt + o_a) * ldy;
                unsigned* yb = g_qkv + ((size_t)b * Ocnt + o_b) * ldy;
                *(uint2*)(ya + c0) = make_uint2(f2tf32(y0), f2tf32(y1));
                *(uint2*)(yb + c0) = make_uint2(f2tf32(y2), f2tf32(y3));
            } else {
                float* ya = outp + ((size_t)b * Ocnt + o_a) * ldy;
                float* yb = outp + ((size_t)b * Ocnt + o_b) * ldy;
                if (c0 < NQ)     { ya[c0]     = y0; yb[c0]     = y2; }
                if (c0 + 1 < NQ) { ya[c0 + 1] = y1; yb[c0 + 1] = y3; }
            }
        }
    }
}

// ---------------------------------------------------------------------------
// Tensor-core attention (round-6 structure). One block per (b,h): 448
// threads = 14 warps, warp w owns n-rows [16w,16w+16). Q A-frags in regs,
// K smem [d][m] pitch 232, V^T smem [m][d] pitch 72, P warp-private [16][36].
// g_qkv already holds tf32 bits -> staging is a pure copy.
// Output stored as tf32 bits into g_att (proj GEMM consumes via mma only).
// ---------------------------------------------------------------------------
#define KPITCH 232
#define VPITCH 72
#define PPITCH 36
#define KS_SZ  (64 * KPITCH)
#define VS_SZ  (224 * VPITCH)
#define PT_SZ  (16 * PPITCH)

__global__ __launch_bounds__(448)
void attn_kernel() {
    extern __shared__ unsigned sm[];
    unsigned* Ks = sm;                  // [d][m]
    unsigned* Vs = sm + KS_SZ;          // [m][d]
    unsigned* Pt = sm + KS_SZ + VS_SZ;  // [warp][16][36]

    const int tid  = threadIdx.x;
    const int lane = tid & 31;
    const int w    = tid >> 5;          // 0..13
    const int row  = lane >> 2;         // 0..7
    const int col  = lane & 3;          // 0..3
    const int b    = blockIdx.x >> 3;
    const int h    = blockIdx.x & 7;
    const int n0   = w * 16;

    const size_t base = ((size_t)b * 3 * CIN + h * HD) * NPAD;
    const unsigned* __restrict__ Qg = g_qkv + base;
    const unsigned* __restrict__ Kg = g_qkv + base + (size_t)CIN * NPAD;
    const unsigned* __restrict__ Vg = g_qkv + base + (size_t)2 * CIN * NPAD;

    // stage K [d][m] and V^T [m][d] (pure copies; data already tf32)
    for (int i = tid; i < HD * NPAD; i += 448) {
        int d = i / NPAD, m = i - d * NPAD;
        Ks[d * KPITCH + m] = Kg[i];
        Vs[m * VPITCH + d] = Vg[i];
    }

    // preload Q A-frags from gmem
    unsigned aQ[8][4];
#pragma unroll
    for (int k8 = 0; k8 < 8; k8++) {
        int d0 = k8 * 8;
        aQ[k8][0] = Qg[(d0 + col) * NPAD + n0 + row];
        aQ[k8][1] = Qg[(d0 + col) * NPAD + n0 + row + 8];
        aQ[k8][2] = Qg[(d0 + col + 4) * NPAD + n0 + row];
        aQ[k8][3] = Qg[(d0 + col + 4) * NPAD + n0 + row + 8];
    }
    __syncthreads();

    const float* __restrict__ bptr = g_biasT + (size_t)h * NQ * NQ;
    unsigned* ptw = Pt + w * PT_SZ;
    const int nb_lo = min(n0 + row, NQ - 1);       // bias row clamp (dead rows)
    const int nb_hi = min(n0 + row + 8, NQ - 1);

    float o[8][4];
#pragma unroll
    for (int i = 0; i < 8; i++)
#pragma unroll
        for (int j = 0; j < 4; j++) o[i][j] = 0.f;
    float ll = 0.f, lh = 0.f;

    for (int mc = 0; mc < 7; mc++) {
        const int m0 = mc * 32;

        // ---- S = Q^T K for columns [m0, m0+32) ----
        float c[4][4];
#pragma unroll
        for (int s = 0; s < 4; s++)
#pragma unroll
            for (int j = 0; j < 4; j++) c[s][j] = 0.f;

#pragma unroll
        for (int k8 = 0; k8 < 8; k8++) {
            const int d8 = k8 * 8 + col;
#pragma unroll
            for (int s = 0; s < 4; s++) {
                const int bb = d8 * KPITCH + m0 + s * 8 + row;
                mma_tf32(c[s], aQ[k8], Ks[bb], Ks[bb + 4 * KPITCH]);
            }
        }

        // exp + bias -> Pt
#pragma unroll
        for (int s = 0; s < 4; s++) {
            const int m_b = m0 + s * 8 + 2 * col;      // even; pair in/out together
            float p0 = 0.f, p1 = 0.f, p2 = 0.f, p3 = 0.f;
            if (m_b < NQ) {
                float2 blo = *(const float2*)(bptr + (size_t)nb_lo * NQ + m_b);
                float2 bhi = *(const float2*)(bptr + (size_t)nb_hi * NQ + m_b);
                p0 = __expf(c[s][0] * 0.125f + blo.x);
                p1 = __expf(c[s][1] * 0.125f + blo.y);
                p2 = __expf(c[s][2] * 0.125f + bhi.x);
                p3 = __expf(c[s][3] * 0.125f + bhi.y);
            }
            ll += p0 + p1;
            lh += p2 + p3;
            int pc = s * 8 + 2 * col;
            ptw[row * PPITCH + pc]           = f2tf32(p0);
            ptw[row * PPITCH + pc + 1]       = f2tf32(p1);
            ptw[(row + 8) * PPITCH + pc]     = f2tf32(p2);
            ptw[(row + 8) * PPITCH + pc + 1] = f2tf32(p3);
        }
        __syncwarp();

        // ---- O += P V^T ----
#pragma unroll
        for (int k4 = 0; k4 < 4; k4++) {
            const int k0 = k4 * 8;
            unsigned a[4];
            a[0] = ptw[row * PPITCH + k0 + col];
            a[1] = ptw[(row + 8) * PPITCH + k0 + col];
            a[2] = ptw[row * PPITCH + k0 + col + 4];
            a[3] = ptw[(row + 8) * PPITCH + k0 + col + 4];
#pragma unroll
            for (int nc = 0; nc < 8; nc++) {
                int bb = (m0 + k0 + col) * VPITCH + nc * 8 + row;
                mma_tf32(o[nc], a, Vs[bb], Vs[bb + 4 * VPITCH]);
            }
        }
        __syncwarp();
    }

    // row sums across the quad
    ll += __shfl_xor_sync(0xffffffffu, ll, 1);
    ll += __shfl_xor_sync(0xffffffffu, ll, 2);
    lh += __shfl_xor_sync(0xffffffffu, lh, 1);
    lh += __shfl_xor_sync(0xffffffffu, lh, 2);
    const float linv_lo = 1.f / ll;
    const float linv_hi = 1.f / lh;

    const int n_lo = n0 + row;
    const int n_hi = n0 + row + 8;
#pragma unroll
    for (int nc = 0; nc < 8; nc++) {
        int d0 = nc * 8 + 2 * col;
#pragma unroll
        for (int j = 0; j < 2; j++) {
            int d = d0 + j;
            if (n_lo < NQ) {
                float v = o[nc][j] * linv_lo;
                float gl = 0.5f * v * (1.f + erff(v * 0.70710678118654752f));
                int flat = h * (NQ * HD) + n_lo * HD + d;
                int cc   = flat / NQ;
                int pos  = flat - cc * NQ;
                g_att[((size_t)b * CIN + cc) * NPAD + pos] = f2tf32(gl);
            }
            if (n_hi < NQ) {
                float v = o[nc][j + 2] * linv_hi;
                float gl = 0.5f * v * (1.f + erff(v * 0.70710678118654752f));
                int flat = h * (NQ * HD) + n_hi * HD + d;
                int cc   = flat / NQ;
                int pos  = flat - cc * NQ;
                g_att[((size_t)b * CIN + cc) * NPAD + pos] = f2tf32(gl);
            }
        }
    }
}

// ---------------------------------------------------------------------------
extern "C" void kernel_launch(void* const* d_in, const int* in_sizes, int n_in,
                              void* d_out, int out_size) {
    const float* x      = (const float*)d_in[0];
    const float* qkv_w  = (const float*)d_in[1];
    const float* bn1_g  = (const float*)d_in[2];
    const float* bn1_b  = (const float*)d_in[3];
    const float* bn1_m  = (const float*)d_in[4];
    const float* bn1_v  = (const float*)d_in[5];
    const float* proj_w = (const float*)d_in[6];
    const float* bn2_g  = (const float*)d_in[7];
    const float* bn2_b  = (const float*)d_in[8];
    const float* bn2_m  = (const float*)d_in[9];
    const float* bn2_v  = (const float*)d_in[10];
    const float* ab     = (const float*)d_in[11];
    const int*   idxs   = (const int*)d_in[12];
    float* out = (float*)d_out;

    const int smem_gemm = (2 * WS_TILE + 2 * XS_TILE) * 4;        // 67584 B
    const int smem_attn = (KS_SZ + VS_SZ + 14 * PT_SZ) * 4;       // 156160 B
    cudaFuncSetAttribute(gemm_tf32<0>,
                         cudaFuncAttributeMaxDynamicSharedMemorySize, smem_gemm);
    cudaFuncSetAttribute(gemm_tf32<1>,
                         cudaFuncAttributeMaxDynamicSharedMemorySize, smem_gemm);
    cudaFuncSetAttribute(attn_kernel,
                         cudaFuncAttributeMaxDynamicSharedMemorySize, smem_attn);

    {   // convert weights to tf32
        int total = (3 * CIN + CIN) * CIN;
        cvt_w_kernel<<<(total + 255) / 256, 256>>>(qkv_w, proj_w);
    }
    {   // pad + convert x to tf32
        int total = B_ * CIN * NQ;
        pad_cvt_x_kernel<<<(total + 255) / 256, 256>>>(x);
    }
    {   // bias gather
        int total = HEADS * NQ * NQ;
        gather_bias_kernel<<<(total + 255) / 256, 256>>>(ab, idxs);
    }
    {   // QKV GEMM + BN1 -> g_qkv (tf32 bits)
        dim3 grid(NPAD / 112, (3 * CIN) / 128, B_);
        gemm_tf32<0><<<grid, 256, smem_gemm>>>(bn1_g, bn1_b, bn1_m, bn1_v, nullptr);
    }
    {   // attention + gelu + scrambled reshape
        attn_kernel<<<B_ * HEADS, 448, smem_attn>>>();
    }
    {   // proj GEMM + BN2 -> d_out
        dim3 grid(NPAD / 112, CIN / 128, B_);
        gemm_tf32<1><<<grid, 256, smem_gemm>>>(bn2_g, bn2_b, bn2_m, bn2_v, out);
    }
}

// round 8
// speedup vs baseline: 3.4902x; 1.0918x over previous
#include <cuda_runtime.h>
#include <math.h>

// ---------------------------------------------------------------------------
// GlobalMHSAWithPosBias: B=128, C=512, RES=14 (N=196), HEADS=8, hd=64
// Round 8: pair-packed GEMM operands (uint2) -> LDS.64 fragment loads.
//   W gmem layout: pair-rows (o, o+8) within 16-row groups.
//   X gmem layout: pair-rows (k, k+4) within 8-row k-blocks.
// Attention core unchanged; its epilogue writes the X pair layout.
// NOTE: never pass __device__ symbols from host code (rounds-3/4 bug).
// ---------------------------------------------------------------------------

#define B_    128
#define CIN   512
#define NQ    196
#define NPAD  224          // 4 * 56 = 2 * 112
#define HEADS 8
#define HD    64
#define EPS_  1e-5f

// pair layouts, element = uint2 (tf32 bit pair)
__device__ unsigned g_xtf [(size_t)B_ * CIN * NPAD];        // x  [b][kpr][n] pairs (BSS 0)
__device__ unsigned g_wtf [(size_t)4 * CIN * CIN];          // qkv_w ++ proj_w, pair rows
__device__ unsigned g_qkv [(size_t)B_ * 3 * CIN * NPAD];    // qkv post-BN1 (plain [c][n])
__device__ unsigned g_att [(size_t)B_ * CIN * NPAD];        // gelu(o), pair layout
__device__ float    g_biasT[HEADS * NQ * NQ];               // bias [h][m][n]

// ---------------------------------------------------------------------------
__device__ __forceinline__ unsigned f2tf32(float f) {
    unsigned u;
    asm("cvt.rna.tf32.f32 %0, %1;" : "=r"(u) : "f"(f));
    return u;
}

__device__ __forceinline__ void mma_tf32(float c[4], const unsigned a[4],
                                         unsigned b0, unsigned b1) {
    asm volatile(
        "mma.sync.aligned.m16n8k8.row.col.f32.tf32.tf32.f32 "
        "{%0,%1,%2,%3}, {%4,%5,%6,%7}, {%8,%9}, {%0,%1,%2,%3};\n"
        : "+f"(c[0]), "+f"(c[1]), "+f"(c[2]), "+f"(c[3])
        : "r"(a[0]), "r"(a[1]), "r"(a[2]), "r"(a[3]), "r"(b0), "r"(b1));
}

__device__ __forceinline__ void cp16(void* dst, const void* src) {
    unsigned s = (unsigned)__cvta_generic_to_shared(dst);
    asm volatile("cp.async.cg.shared.global [%0], [%1], 16;" :: "r"(s), "l"(src));
}
__device__ __forceinline__ void cp_commit() {
    asm volatile("cp.async.commit_group;");
}
template <int N>
__device__ __forceinline__ void cp_wait() {
    asm volatile("cp.async.wait_group %0;" :: "n"(N));
}

// ---------------------------------------------------------------------------
// prologue converters (write pair layouts)
// ---------------------------------------------------------------------------
__global__ void cvt_w_kernel(const float* __restrict__ qkv_w,
                             const float* __restrict__ proj_w) {
    int i = blockIdx.x * blockDim.x + threadIdx.x;
    const int n1 = 3 * CIN * CIN, total = n1 + CIN * CIN;
    if (i >= total) return;
    float v;
    int o, k, basepr;
    if (i < n1) { v = qkv_w[i];      o = i / CIN;        k = i % CIN;        basepr = 0; }
    else        { v = proj_w[i - n1]; o = (i - n1) / CIN; k = (i - n1) % CIN; basepr = 768; }
    int og = o >> 4, orr = o & 15;
    int pr = basepr + og * 8 + (orr & 7);
    int comp = orr >> 3;
    g_wtf[(((size_t)pr * CIN) + k) * 2 + comp] = f2tf32(v);
}

__global__ void pad_cvt_x_kernel(const float* __restrict__ x) {
    int i = blockIdx.x * blockDim.x + threadIdx.x;
    const int total = B_ * CIN * NQ;
    if (i >= total) return;
    int n  = i % NQ;
    int rc = i / NQ;
    int b  = rc / CIN, c = rc % CIN;
    int prx  = (c >> 3) * 4 + (c & 3);
    int comp = (c & 7) >> 2;
    g_xtf[(((size_t)b * (CIN / 2) + prx) * NPAD + n) * 2 + comp] = f2tf32(x[i]);
}

__global__ void gather_bias_kernel(const float* __restrict__ ab,
                                   const int*   __restrict__ idxs) {
    int i = blockIdx.x * blockDim.x + threadIdx.x;
    const int total = HEADS * NQ * NQ;
    if (i >= total) return;
    int stride = (idxs[1] == 0 && idxs[3] == 0) ? 2 : 1;   // int64 detection
    int h = i / (NQ * NQ);
    int j = i - h * (NQ * NQ);
    g_biasT[i] = ab[h * NQ + idxs[(size_t)j * stride]];
}

// ---------------------------------------------------------------------------
// tf32 GEMM + fused BN affine; pair-packed operands, cp.async 2-stage.
// MODE 0: X=g_xtf pairs, W=qkv part,  Y=g_qkv (plain tf32 bits, ldy=224)
// MODE 1: X=g_att pairs, W=proj part, Y=outp  (f32, ldy=196, guarded)
// BM=128, BN=112, BK=32, 256 threads (8 warps, 4m x 2n), warp tile 32x56.
// ---------------------------------------------------------------------------
#define WP2 36          // uint2 pitch, W pair tile (64 pair-rows x 32 k)
#define XP2 116         // uint2 pitch, X pair tile (16 pair-rows x 112 n)
#define WS_T2 (64 * WP2)
#define XS_T2 (16 * XP2)

template <int MODE>
__global__ __launch_bounds__(256)
void gemm_tf32(const float* __restrict__ gamma, const float* __restrict__ beta,
               const float* __restrict__ mean,  const float* __restrict__ var,
               float* __restrict__ outp) {
    extern __shared__ uint2 smg[];
    uint2* Ws = smg;                  // 2 stages
    uint2* Xs = smg + 2 * WS_T2;      // 2 stages

    const uint2* __restrict__ X2 = (MODE == 0) ? (const uint2*)g_xtf
                                               : (const uint2*)g_att;
    const uint2* __restrict__ W2 = (const uint2*)g_wtf
                                   + (MODE == 0 ? 0 : (size_t)768 * CIN);
    const int Ocnt = (MODE == 0) ? 3 * CIN : CIN;
    const int ldy  = (MODE == 0) ? NPAD : NQ;

    const int tid  = threadIdx.x;
    const int lane = tid & 31;
    const int wid  = tid >> 5;
    const int wm   = wid & 3;
    const int n0w  = (wid >> 2) * 56;

    const int b  = blockIdx.z;
    const int o0 = blockIdx.y * 128;
    const int n0 = blockIdx.x * 112;

    const uint2* __restrict__ Wp = W2 + (size_t)(o0 / 2) * CIN;          // 64 pair-rows
    const uint2* __restrict__ Xp = X2 + (size_t)b * (CIN / 2) * NPAD + n0;

    float acc[2][7][4];
#pragma unroll
    for (int i = 0; i < 2; i++)
#pragma unroll
        for (int j = 0; j < 7; j++)
#pragma unroll
            for (int k = 0; k < 4; k++) acc[i][j][k] = 0.f;

    const int row = lane >> 2;
    const int col = lane & 3;

    auto load_tiles = [&](int kk, int st) {     // kk = k offset (multiple of 32)
        uint2* ws = Ws + st * WS_T2;
        uint2* xs = Xs + st * XS_T2;
#pragma unroll
        for (int i = tid; i < 1024; i += 256) {       // W: 64 pr x 32 k
            int r = i >> 4, c2 = (i & 15) * 2;
            cp16(ws + r * WP2 + c2, Wp + (size_t)r * CIN + kk + c2);
        }
#pragma unroll
        for (int i = tid; i < 896; i += 256) {        // X: 16 pr x 112 n
            int r = i / 56, c2 = (i % 56) * 2;
            cp16(xs + r * XP2 + c2, Xp + (size_t)(kk / 2 + r) * NPAD + c2);
        }
        cp_commit();
    };

    load_tiles(0, 0);

    for (int it = 0; it < 16; ++it) {
        const int cur = it & 1;
        if (it + 1 < 16) {
            load_tiles((it + 1) * 32, (it + 1) & 1);
            cp_wait<1>();
        } else {
            cp_wait<0>();
        }
        __syncthreads();

        const uint2* ws = Ws + cur * WS_T2;
        const uint2* xs = Xs + cur * XS_T2;
#pragma unroll
        for (int ks = 0; ks < 4; ks++) {
            const int k0 = ks * 8;
            unsigned a[2][4];
#pragma unroll
            for (int mt = 0; mt < 2; mt++) {
                int pr = (wm * 2 + mt) * 8 + row;
                uint2 A01 = ws[pr * WP2 + k0 + col];
                uint2 A23 = ws[pr * WP2 + k0 + col + 4];
                a[mt][0] = A01.x; a[mt][1] = A01.y;
                a[mt][2] = A23.x; a[mt][3] = A23.y;
            }
#pragma unroll
            for (int nt = 0; nt < 7; nt++) {
                uint2 Bf = xs[(ks * 4 + col) * XP2 + n0w + nt * 8 + row];
                mma_tf32(acc[0][nt], a[0], Bf.x, Bf.y);
                mma_tf32(acc[1][nt], a[1], Bf.x, Bf.y);
            }
        }
        __syncthreads();
    }

    // epilogue: BN affine + store
#pragma unroll
    for (int mt = 0; mt < 2; mt++) {
        int o_a = o0 + wm * 32 + mt * 16 + row;
        int o_b = o_a + 8;
        float inv_a = gamma[o_a] * rsqrtf(var[o_a] + EPS_);
        float sh_a  = beta[o_a] - mean[o_a] * inv_a;
        float inv_b = gamma[o_b] * rsqrtf(var[o_b] + EPS_);
        float sh_b  = beta[o_b] - mean[o_b] * inv_b;
#pragma unroll
        for (int nt = 0; nt < 7; nt++) {
            int c0 = n0 + n0w + nt * 8 + col * 2;
            float y0 = acc[mt][nt][0] * inv_a + sh_a;
            float y1 = acc[mt][nt][1] * inv_a + sh_a;
            float y2 = acc[mt][nt][2] * inv_b + sh_b;
            float y3 = acc[mt][nt][3] * inv_b + sh_b;
            if (MODE == 0) {
                unsigned* ya = g_qkv + ((size_t)b * Ocnt + o_a) * ldy;
                unsigned* yb = g_qkv + ((size_t)b * Ocnt + o_b) * ldy;
                *(uint2*)(ya + c0) = make_uint2(f2tf32(y0), f2tf32(y1));
                *(uint2*)(yb + c0) = make_uint2(f2tf32(y2), f2tf32(y3));
            } else {
                float* ya = outp + ((size_t)b * Ocnt + o_a) * ldy;
                float* yb = outp + ((size_t)b * Ocnt + o_b) * ldy;
                if (c0 < NQ)     { ya[c0]     = y0; yb[c0]     = y2; }
                if (c0 + 1 < NQ) { ya[c0 + 1] = y1; yb[c0 + 1] = y3; }
            }
        }
    }
}

// ---------------------------------------------------------------------------
// Tensor-core attention (round-7 core, epilogue writes X pair layout).
// One block per (b,h): 448 threads = 14 warps, warp w owns n-rows [16w,16w+16).
// ---------------------------------------------------------------------------
#define KPITCH 232
#define VPITCH 72
#define PPITCH 36
#define KS_SZ  (64 * KPITCH)
#define VS_SZ  (224 * VPITCH)
#define PT_SZ  (16 * PPITCH)

__global__ __launch_bounds__(448)
void attn_kernel() {
    extern __shared__ unsigned sm[];
    unsigned* Ks = sm;                  // [d][m]
    unsigned* Vs = sm + KS_SZ;          // [m][d]
    unsigned* Pt = sm + KS_SZ + VS_SZ;  // [warp][16][36]

    const int tid  = threadIdx.x;
    const int lane = tid & 31;
    const int w    = tid >> 5;          // 0..13
    const int row  = lane >> 2;         // 0..7
    const int col  = lane & 3;          // 0..3
    const int b    = blockIdx.x >> 3;
    const int h    = blockIdx.x & 7;
    const int n0   = w * 16;

    const size_t base = ((size_t)b * 3 * CIN + h * HD) * NPAD;
    const unsigned* __restrict__ Qg = g_qkv + base;
    const unsigned* __restrict__ Kg = g_qkv + base + (size_t)CIN * NPAD;
    const unsigned* __restrict__ Vg = g_qkv + base + (size_t)2 * CIN * NPAD;

    for (int i = tid; i < HD * NPAD; i += 448) {
        int d = i / NPAD, m = i - d * NPAD;
        Ks[d * KPITCH + m] = Kg[i];
        Vs[m * VPITCH + d] = Vg[i];
    }

    unsigned aQ[8][4];
#pragma unroll
    for (int k8 = 0; k8 < 8; k8++) {
        int d0 = k8 * 8;
        aQ[k8][0] = Qg[(d0 + col) * NPAD + n0 + row];
        aQ[k8][1] = Qg[(d0 + col) * NPAD + n0 + row + 8];
        aQ[k8][2] = Qg[(d0 + col + 4) * NPAD + n0 + row];
        aQ[k8][3] = Qg[(d0 + col + 4) * NPAD + n0 + row + 8];
    }
    __syncthreads();

    const float* __restrict__ bptr = g_biasT + (size_t)h * NQ * NQ;
    unsigned* ptw = Pt + w * PT_SZ;
    const int nb_lo = min(n0 + row, NQ - 1);
    const int nb_hi = min(n0 + row + 8, NQ - 1);

    float o[8][4];
#pragma unroll
    for (int i = 0; i < 8; i++)
#pragma unroll
        for (int j = 0; j < 4; j++) o[i][j] = 0.f;
    float ll = 0.f, lh = 0.f;

    for (int mc = 0; mc < 7; mc++) {
        const int m0 = mc * 32;

        float c[4][4];
#pragma unroll
        for (int s = 0; s < 4; s++)
#pragma unroll
            for (int j = 0; j < 4; j++) c[s][j] = 0.f;

#pragma unroll
        for (int k8 = 0; k8 < 8; k8++) {
            const int d8 = k8 * 8 + col;
#pragma unroll
            for (int s = 0; s < 4; s++) {
                const int bb = d8 * KPITCH + m0 + s * 8 + row;
                mma_tf32(c[s], aQ[k8], Ks[bb], Ks[bb + 4 * KPITCH]);
            }
        }

#pragma unroll
        for (int s = 0; s < 4; s++) {
            const int m_b = m0 + s * 8 + 2 * col;
            float p0 = 0.f, p1 = 0.f, p2 = 0.f, p3 = 0.f;
            if (m_b < NQ) {
                float2 blo = *(const float2*)(bptr + (size_t)nb_lo * NQ + m_b);
                float2 bhi = *(const float2*)(bptr + (size_t)nb_hi * NQ + m_b);
                p0 = __expf(c[s][0] * 0.125f + blo.x);
                p1 = __expf(c[s][1] * 0.125f + blo.y);
                p2 = __expf(c[s][2] * 0.125f + bhi.x);
                p3 = __expf(c[s][3] * 0.125f + bhi.y);
            }
            ll += p0 + p1;
            lh += p2 + p3;
            int pc = s * 8 + 2 * col;
            ptw[row * PPITCH + pc]           = f2tf32(p0);
            ptw[row * PPITCH + pc + 1]       = f2tf32(p1);
            ptw[(row + 8) * PPITCH + pc]     = f2tf32(p2);
            ptw[(row + 8) * PPITCH + pc + 1] = f2tf32(p3);
        }
        __syncwarp();

#pragma unroll
        for (int k4 = 0; k4 < 4; k4++) {
            const int k0 = k4 * 8;
            unsigned a[4];
            a[0] = ptw[row * PPITCH + k0 + col];
            a[1] = ptw[(row + 8) * PPITCH + k0 + col];
            a[2] = ptw[row * PPITCH + k0 + col + 4];
            a[3] = ptw[(row + 8) * PPITCH + k0 + col + 4];
#pragma unroll
            for (int nc = 0; nc < 8; nc++) {
                int bb = (m0 + k0 + col) * VPITCH + nc * 8 + row;
                mma_tf32(o[nc], a, Vs[bb], Vs[bb + 4 * VPITCH]);
            }
        }
        __syncwarp();
    }

    ll += __shfl_xor_sync(0xffffffffu, ll, 1);
    ll += __shfl_xor_sync(0xffffffffu, ll, 2);
    lh += __shfl_xor_sync(0xffffffffu, lh, 1);
    lh += __shfl_xor_sync(0xffffffffu, lh, 2);
    const float linv_lo = 1.f / ll;
    const float linv_hi = 1.f / lh;

    const int n_lo = n0 + row;
    const int n_hi = n0 + row + 8;
#pragma unroll
    for (int nc = 0; nc < 8; nc++) {
        int d0 = nc * 8 + 2 * col;
#pragma unroll
        for (int j = 0; j < 2; j++) {
            int d = d0 + j;
            if (n_lo < NQ) {
                float v = o[nc][j] * linv_lo;
                float gl = 0.5f * v * (1.f + erff(v * 0.70710678118654752f));
                int flat = h * (NQ * HD) + n_lo * HD + d;
                int cc   = flat / NQ;
                int pos  = flat - cc * NQ;
                int prx  = (cc >> 3) * 4 + (cc & 3);
                int comp = (cc & 7) >> 2;
                g_att[(((size_t)b * (CIN / 2) + prx) * NPAD + pos) * 2 + comp]
                    = f2tf32(gl);
            }
            if (n_hi < NQ) {
                float v = o[nc][j + 2] * linv_hi;
                float gl = 0.5f * v * (1.f + erff(v * 0.70710678118654752f));
                int flat = h * (NQ * HD) + n_hi * HD + d;
                int cc   = flat / NQ;
                int pos  = flat - cc * NQ;
                int prx  = (cc >> 3) * 4 + (cc & 3);
                int comp = (cc & 7) >> 2;
                g_att[(((size_t)b * (CIN / 2) + prx) * NPAD + pos) * 2 + comp]
                    = f2tf32(gl);
            }
        }
    }
}

// ---------------------------------------------------------------------------
extern "C" void kernel_launch(void* const* d_in, const int* in_sizes, int n_in,
                              void* d_out, int out_size) {
    const float* x      = (const float*)d_in[0];
    const float* qkv_w  = (const float*)d_in[1];
    const float* bn1_g  = (const float*)d_in[2];
    const float* bn1_b  = (const float*)d_in[3];
    const float* bn1_m  = (const float*)d_in[4];
    const float* bn1_v  = (const float*)d_in[5];
    const float* proj_w = (const float*)d_in[6];
    const float* bn2_g  = (const float*)d_in[7];
    const float* bn2_b  = (const float*)d_in[8];
    const float* bn2_m  = (const float*)d_in[9];
    const float* bn2_v  = (const float*)d_in[10];
    const float* ab     = (const float*)d_in[11];
    const int*   idxs   = (const int*)d_in[12];
    float* out = (float*)d_out;

    const int smem_gemm = (2 * WS_T2 + 2 * XS_T2) * 8;            // 66560 B
    const int smem_attn = (KS_SZ + VS_SZ + 14 * PT_SZ) * 4;       // 156160 B
    cudaFuncSetAttribute(gemm_tf32<0>,
                         cudaFuncAttributeMaxDynamicSharedMemorySize, smem_gemm);
    cudaFuncSetAttribute(gemm_tf32<1>,
                         cudaFuncAttributeMaxDynamicSharedMemorySize, smem_gemm);
    cudaFuncSetAttribute(attn_kernel,
                         cudaFuncAttributeMaxDynamicSharedMemorySize, smem_attn);

    {   // convert weights to tf32 pair layout
        int total = 4 * CIN * CIN;
        cvt_w_kernel<<<(total + 255) / 256, 256>>>(qkv_w, proj_w);
    }
    {   // pad + convert x to tf32 pair layout
        int total = B_ * CIN * NQ;
        pad_cvt_x_kernel<<<(total + 255) / 256, 256>>>(x);
    }
    {   // bias gather
        int total = HEADS * NQ * NQ;
        gather_bias_kernel<<<(total + 255) / 256, 256>>>(ab, idxs);
    }
    {   // QKV GEMM + BN1 -> g_qkv
        dim3 grid(NPAD / 112, (3 * CIN) / 128, B_);
        gemm_tf32<0><<<grid, 256, smem_gemm>>>(bn1_g, bn1_b, bn1_m, bn1_v, nullptr);
    }
    {   // attention + gelu + scrambled reshape
        attn_kernel<<<B_ * HEADS, 448, smem_attn>>>();
    }
    {   // proj GEMM + BN2 -> d_out
        dim3 grid(NPAD / 112, CIN / 128, B_);
        gemm_tf32<1><<<grid, 256, smem_gemm>>>(bn2_g, bn2_b, bn2_m, bn2_v, out);
    }
}

// round 9
// speedup vs baseline: 4.6220x; 1.3243x over previous
#include <cuda_runtime.h>
#include <cuda_fp16.h>
#include <math.h>

// ---------------------------------------------------------------------------
// GlobalMHSAWithPosBias: B=128, C=512, RES=14 (N=196), HEADS=8, hd=64
// Round 9: GEMMs switch to fp16 mma.m16n8k16 (same 10-bit mantissa as tf32;
// all operands range-safe). BK=64 (8 iterations). Attention core unchanged
// (tf32, g_qkv tf32-bits); only its epilogue writes fp16 g_att pair layout.
// NOTE: never pass __device__ symbols from host code (rounds-3/4 bug).
// ---------------------------------------------------------------------------

#define B_    128
#define CIN   512
#define NQ    196
#define NPAD  224          // 4 * 56 = 2 * 112
#define HEADS 8
#define HD    64
#define EPS_  1e-5f

// fp16 GEMM operand layouts:
//  g_wh halves: idx = pr*1024 + kp*4 + comp*2 + (k&1)
//    pr = base + (o>>4)*8 + (o&7), comp = (o>>3)&1   [qkv: base 0, proj: 768]
//    as uint2[pr][256 kp]: .x = h2{W[o][2kp..]}, .y = h2{W[o+8][2kp..]}
//  g_xh / g_att halves: uint2[b][128 sb][224 n]
//    sb = (kp>>3)*4 + (kp&3), .x/.y selected by (kp>>2)&1; halves by (c&1)
__device__ unsigned g_wh [(size_t)1024 * 256 * 2];          // 2 MB
__device__ unsigned g_xh [(size_t)B_ * 128 * NPAD * 2];     // 29 MB (BSS 0)
__device__ unsigned g_att[(size_t)B_ * 128 * NPAD * 2];     // 29 MB (BSS 0)
__device__ unsigned g_qkv[(size_t)B_ * 3 * CIN * NPAD];     // qkv post-BN1, tf32 bits
__device__ float    g_biasT[HEADS * NQ * NQ];               // bias [h][m][n]

// ---------------------------------------------------------------------------
__device__ __forceinline__ unsigned f2tf32(float f) {
    unsigned u;
    asm("cvt.rna.tf32.f32 %0, %1;" : "=r"(u) : "f"(f));
    return u;
}

__device__ __forceinline__ void mma_tf32(float c[4], const unsigned a[4],
                                         unsigned b0, unsigned b1) {
    asm volatile(
        "mma.sync.aligned.m16n8k8.row.col.f32.tf32.tf32.f32 "
        "{%0,%1,%2,%3}, {%4,%5,%6,%7}, {%8,%9}, {%0,%1,%2,%3};\n"
        : "+f"(c[0]), "+f"(c[1]), "+f"(c[2]), "+f"(c[3])
        : "r"(a[0]), "r"(a[1]), "r"(a[2]), "r"(a[3]), "r"(b0), "r"(b1));
}

__device__ __forceinline__ void mma_f16(float c[4], const unsigned a[4],
                                        unsigned b0, unsigned b1) {
    asm volatile(
        "mma.sync.aligned.m16n8k16.row.col.f32.f16.f16.f32 "
        "{%0,%1,%2,%3}, {%4,%5,%6,%7}, {%8,%9}, {%0,%1,%2,%3};\n"
        : "+f"(c[0]), "+f"(c[1]), "+f"(c[2]), "+f"(c[3])
        : "r"(a[0]), "r"(a[1]), "r"(a[2]), "r"(a[3]), "r"(b0), "r"(b1));
}

__device__ __forceinline__ void cp16(void* dst, const void* src) {
    unsigned s = (unsigned)__cvta_generic_to_shared(dst);
    asm volatile("cp.async.cg.shared.global [%0], [%1], 16;" :: "r"(s), "l"(src));
}
__device__ __forceinline__ void cp_commit() {
    asm volatile("cp.async.commit_group;");
}
template <int N>
__device__ __forceinline__ void cp_wait() {
    asm volatile("cp.async.wait_group %0;" :: "n"(N));
}

// ---------------------------------------------------------------------------
// prologue converters
// ---------------------------------------------------------------------------
__global__ void cvt_w_kernel(const float* __restrict__ qkv_w,
                             const float* __restrict__ proj_w) {
    int i = blockIdx.x * blockDim.x + threadIdx.x;
    const int n1 = 3 * CIN * CIN, total = n1 + CIN * CIN;
    if (i >= total) return;
    float v;
    int o, k, basepr;
    if (i < n1) { v = qkv_w[i];       o = i / CIN;        k = i % CIN;        basepr = 0; }
    else        { v = proj_w[i - n1]; o = (i - n1) / CIN; k = (i - n1) % CIN; basepr = 768; }
    int pr   = basepr + (o >> 4) * 8 + (o & 7);
    int comp = (o >> 3) & 1;
    int kp   = k >> 1;
    ((__half*)g_wh)[(size_t)pr * 1024 + kp * 4 + comp * 2 + (k & 1)]
        = __float2half_rn(v);
}

__global__ void pad_cvt_x_kernel(const float* __restrict__ x) {
    int i = blockIdx.x * blockDim.x + threadIdx.x;
    const int total = B_ * CIN * NQ;
    if (i >= total) return;
    int n  = i % NQ;
    int rc = i / NQ;
    int b  = rc / CIN, c = rc % CIN;
    int kp = c >> 1;
    int sb = (kp >> 3) * 4 + (kp & 3);
    int hi = (kp >> 2) & 1;
    ((__half*)g_xh)[(((size_t)b * 128 + sb) * NPAD + n) * 4 + hi * 2 + (c & 1)]
        = __float2half_rn(x[i]);
}

__global__ void gather_bias_kernel(const float* __restrict__ ab,
                                   const int*   __restrict__ idxs) {
    int i = blockIdx.x * blockDim.x + threadIdx.x;
    const int total = HEADS * NQ * NQ;
    if (i >= total) return;
    int stride = (idxs[1] == 0 && idxs[3] == 0) ? 2 : 1;   // int64 detection
    int h = i / (NQ * NQ);
    int j = i - h * (NQ * NQ);
    g_biasT[i] = ab[h * NQ + idxs[(size_t)j * stride]];
}

// ---------------------------------------------------------------------------
// fp16 GEMM + fused BN affine; pair-packed operands, cp.async 2-stage, BK=64.
// MODE 0: X=g_xh,  W pr base 0,   Y=g_qkv (tf32 bits, ldy=224)
// MODE 1: X=g_att, W pr base 768, Y=outp  (f32, ldy=196, guarded)
// BM=128, BN=112, BK=64, 256 threads (8 warps, 4m x 2n), warp tile 32x56.
// ---------------------------------------------------------------------------
#define WP2 36          // uint2 pitch, W tile [64 pr][32 kp]
#define XP2 116         // uint2 pitch, X tile [16 sb][112 n]
#define WS_T2 (64 * WP2)
#define XS_T2 (16 * XP2)

template <int MODE>
__global__ __launch_bounds__(256)
void gemm_f16(const float* __restrict__ gamma, const float* __restrict__ beta,
              const float* __restrict__ mean,  const float* __restrict__ var,
              float* __restrict__ outp) {
    extern __shared__ uint2 smg[];
    uint2* Ws = smg;                  // 2 stages
    uint2* Xs = smg + 2 * WS_T2;      // 2 stages

    const uint2* __restrict__ X2 = (MODE == 0) ? (const uint2*)g_xh
                                               : (const uint2*)g_att;
    const uint2* __restrict__ W2 = (const uint2*)g_wh
                                   + (MODE == 0 ? 0 : (size_t)768 * 256);
    const int Ocnt = (MODE == 0) ? 3 * CIN : CIN;
    const int ldy  = (MODE == 0) ? NPAD : NQ;

    const int tid  = threadIdx.x;
    const int lane = tid & 31;
    const int wid  = tid >> 5;
    const int wm   = wid & 3;
    const int n0w  = (wid >> 2) * 56;

    const int b  = blockIdx.z;
    const int o0 = blockIdx.y * 128;
    const int n0 = blockIdx.x * 112;

    const uint2* __restrict__ Wp = W2 + (size_t)(o0 / 2) * 256;   // pr rows, 256 kp each
    const uint2* __restrict__ Xp = X2 + ((size_t)b * 128) * NPAD + n0;

    float acc[2][7][4];
#pragma unroll
    for (int i = 0; i < 2; i++)
#pragma unroll
        for (int j = 0; j < 7; j++)
#pragma unroll
            for (int k = 0; k < 4; k++) acc[i][j][k] = 0.f;

    const int row = lane >> 2;
    const int col = lane & 3;

    auto load_tiles = [&](int it, int st) {     // it = 64-k tile index (0..7)
        uint2* ws = Ws + st * WS_T2;
        uint2* xs = Xs + st * XS_T2;
#pragma unroll
        for (int i = tid; i < 1024; i += 256) {       // W: 64 pr x 32 kp
            int r = i >> 4, c2 = (i & 15) * 2;
            cp16(ws + r * WP2 + c2, Wp + (size_t)r * 256 + it * 32 + c2);
        }
#pragma unroll
        for (int i = tid; i < 896; i += 256) {        // X: 16 sb x 112 n
            int r = i / 56, c2 = (i % 56) * 2;
            cp16(xs + r * XP2 + c2, Xp + (size_t)(it * 16 + r) * NPAD + c2);
        }
        cp_commit();
    };

    load_tiles(0, 0);

    for (int it = 0; it < 8; ++it) {
        const int cur = it & 1;
        if (it + 1 < 8) {
            load_tiles(it + 1, (it + 1) & 1);
            cp_wait<1>();
        } else {
            cp_wait<0>();
        }
        __syncthreads();

        const uint2* ws = Ws + cur * WS_T2;
        const uint2* xs = Xs + cur * XS_T2;
#pragma unroll
        for (int ks = 0; ks < 4; ks++) {        // 4 k16-steps per 64-k tile
            unsigned a[2][4];
#pragma unroll
            for (int mt = 0; mt < 2; mt++) {
                int pr = (wm * 2 + mt) * 8 + row;
                uint2 A01 = ws[pr * WP2 + ks * 8 + col];
                uint2 A23 = ws[pr * WP2 + ks * 8 + col + 4];
                a[mt][0] = A01.x; a[mt][1] = A01.y;
                a[mt][2] = A23.x; a[mt][3] = A23.y;
            }
#pragma unroll
            for (int nt = 0; nt < 7; nt++) {
                uint2 Bf = xs[(ks * 4 + col) * XP2 + n0w + nt * 8 + row];
                mma_f16(acc[0][nt], a[0], Bf.x, Bf.y);
                mma_f16(acc[1][nt], a[1], Bf.x, Bf.y);
            }
        }
        __syncthreads();
    }

    // epilogue: BN affine + store
#pragma unroll
    for (int mt = 0; mt < 2; mt++) {
        int o_a = o0 + wm * 32 + mt * 16 + row;
        int o_b = o_a + 8;
        float inv_a = gamma[o_a] * rsqrtf(var[o_a] + EPS_);
        float sh_a  = beta[o_a] - mean[o_a] * inv_a;
        float inv_b = gamma[o_b] * rsqrtf(var[o_b] + EPS_);
        float sh_b  = beta[o_b] - mean[o_b] * inv_b;
#pragma unroll
        for (int nt = 0; nt < 7; nt++) {
            int c0 = n0 + n0w + nt * 8 + col * 2;
            float y0 = acc[mt][nt][0] * inv_a + sh_a;
            float y1 = acc[mt][nt][1] * inv_a + sh_a;
            float y2 = acc[mt][nt][2] * inv_b + sh_b;
            float y3 = acc[mt][nt][3] * inv_b + sh_b;
            if (MODE == 0) {
                unsigned* ya = g_qkv + ((size_t)b * Ocnt + o_a) * ldy;
                unsigned* yb = g_qkv + ((size_t)b * Ocnt + o_b) * ldy;
                *(uint2*)(ya + c0) = make_uint2(f2tf32(y0), f2tf32(y1));
                *(uint2*)(yb + c0) = make_uint2(f2tf32(y2), f2tf32(y3));
            } else {
                float* ya = outp + ((size_t)b * Ocnt + o_a) * ldy;
                float* yb = outp + ((size_t)b * Ocnt + o_b) * ldy;
                if (c0 < NQ)     { ya[c0]     = y0; yb[c0]     = y2; }
                if (c0 + 1 < NQ) { ya[c0 + 1] = y1; yb[c0 + 1] = y3; }
            }
        }
    }
}

// ---------------------------------------------------------------------------
// Tensor-core attention (round-8 core, tf32, unchanged math). Epilogue now
// writes fp16 halves into g_att's pair layout.
// ---------------------------------------------------------------------------
#define KPITCH 232
#define VPITCH 72
#define PPITCH 36
#define KS_SZ  (64 * KPITCH)
#define VS_SZ  (224 * VPITCH)
#define PT_SZ  (16 * PPITCH)

__global__ __launch_bounds__(448)
void attn_kernel() {
    extern __shared__ unsigned sm[];
    unsigned* Ks = sm;                  // [d][m]
    unsigned* Vs = sm + KS_SZ;          // [m][d]
    unsigned* Pt = sm + KS_SZ + VS_SZ;  // [warp][16][36]

    const int tid  = threadIdx.x;
    const int lane = tid & 31;
    const int w    = tid >> 5;          // 0..13
    const int row  = lane >> 2;         // 0..7
    const int col  = lane & 3;          // 0..3
    const int b    = blockIdx.x >> 3;
    const int h    = blockIdx.x & 7;
    const int n0   = w * 16;

    const size_t base = ((size_t)b * 3 * CIN + h * HD) * NPAD;
    const unsigned* __restrict__ Qg = g_qkv + base;
    const unsigned* __restrict__ Kg = g_qkv + base + (size_t)CIN * NPAD;
    const unsigned* __restrict__ Vg = g_qkv + base + (size_t)2 * CIN * NPAD;

    for (int i = tid; i < HD * NPAD; i += 448) {
        int d = i / NPAD, m = i - d * NPAD;
        Ks[d * KPITCH + m] = Kg[i];
        Vs[m * VPITCH + d] = Vg[i];
    }

    unsigned aQ[8][4];
#pragma unroll
    for (int k8 = 0; k8 < 8; k8++) {
        int d0 = k8 * 8;
        aQ[k8][0] = Qg[(d0 + col) * NPAD + n0 + row];
        aQ[k8][1] = Qg[(d0 + col) * NPAD + n0 + row + 8];
        aQ[k8][2] = Qg[(d0 + col + 4) * NPAD + n0 + row];
        aQ[k8][3] = Qg[(d0 + col + 4) * NPAD + n0 + row + 8];
    }
    __syncthreads();

    const float* __restrict__ bptr = g_biasT + (size_t)h * NQ * NQ;
    unsigned* ptw = Pt + w * PT_SZ;
    const int nb_lo = min(n0 + row, NQ - 1);
    const int nb_hi = min(n0 + row + 8, NQ - 1);

    float o[8][4];
#pragma unroll
    for (int i = 0; i < 8; i++)
#pragma unroll
        for (int j = 0; j < 4; j++) o[i][j] = 0.f;
    float ll = 0.f, lh = 0.f;

    for (int mc = 0; mc < 7; mc++) {
        const int m0 = mc * 32;

        float c[4][4];
#pragma unroll
        for (int s = 0; s < 4; s++)
#pragma unroll
            for (int j = 0; j < 4; j++) c[s][j] = 0.f;

#pragma unroll
        for (int k8 = 0; k8 < 8; k8++) {
            const int d8 = k8 * 8 + col;
#pragma unroll
            for (int s = 0; s < 4; s++) {
                const int bb = d8 * KPITCH + m0 + s * 8 + row;
                mma_tf32(c[s], aQ[k8], Ks[bb], Ks[bb + 4 * KPITCH]);
            }
        }

#pragma unroll
        for (int s = 0; s < 4; s++) {
            const int m_b = m0 + s * 8 + 2 * col;
            float p0 = 0.f, p1 = 0.f, p2 = 0.f, p3 = 0.f;
            if (m_b < NQ) {
                float2 blo = *(const float2*)(bptr + (size_t)nb_lo * NQ + m_b);
                float2 bhi = *(const float2*)(bptr + (size_t)nb_hi * NQ + m_b);
                p0 = __expf(c[s][0] * 0.125f + blo.x);
                p1 = __expf(c[s][1] * 0.125f + blo.y);
                p2 = __expf(c[s][2] * 0.125f + bhi.x);
                p3 = __expf(c[s][3] * 0.125f + bhi.y);
            }
            ll += p0 + p1;
            lh += p2 + p3;
            int pc = s * 8 + 2 * col;
            ptw[row * PPITCH + pc]           = f2tf32(p0);
            ptw[row * PPITCH + pc + 1]       = f2tf32(p1);
            ptw[(row + 8) * PPITCH + pc]     = f2tf32(p2);
            ptw[(row + 8) * PPITCH + pc + 1] = f2tf32(p3);
        }
        __syncwarp();

#pragma unroll
        for (int k4 = 0; k4 < 4; k4++) {
            const int k0 = k4 * 8;
            unsigned a[4];
            a[0] = ptw[row * PPITCH + k0 + col];
            a[1] = ptw[(row + 8) * PPITCH + k0 + col];
            a[2] = ptw[row * PPITCH + k0 + col + 4];
            a[3] = ptw[(row + 8) * PPITCH + k0 + col + 4];
#pragma unroll
            for (int nc = 0; nc < 8; nc++) {
                int bb = (m0 + k0 + col) * VPITCH + nc * 8 + row;
                mma_tf32(o[nc], a, Vs[bb], Vs[bb + 4 * VPITCH]);
            }
        }
        __syncwarp();
    }

    ll += __shfl_xor_sync(0xffffffffu, ll, 1);
    ll += __shfl_xor_sync(0xffffffffu, ll, 2);
    lh += __shfl_xor_sync(0xffffffffu, lh, 1);
    lh += __shfl_xor_sync(0xffffffffu, lh, 2);
    const float linv_lo = 1.f / ll;
    const float linv_hi = 1.f / lh;

    __half* ap = (__half*)g_att;
    const int n_lo = n0 + row;
    const int n_hi = n0 + row + 8;
#pragma unroll
    for (int nc = 0; nc < 8; nc++) {
        int d0 = nc * 8 + 2 * col;
#pragma unroll
        for (int j = 0; j < 2; j++) {
            int d = d0 + j;
            if (n_lo < NQ) {
                float v = o[nc][j] * linv_lo;
                float gl = 0.5f * v * (1.f + erff(v * 0.70710678118654752f));
                int flat = h * (NQ * HD) + n_lo * HD + d;
                int cc   = flat / NQ;
                int pos  = flat - cc * NQ;
                int kp   = cc >> 1;
                int sb   = (kp >> 3) * 4 + (kp & 3);
                int hi   = (kp >> 2) & 1;
                ap[(((size_t)b * 128 + sb) * NPAD + pos) * 4 + hi * 2 + (cc & 1)]
                    = __float2half_rn(gl);
            }
            if (n_hi < NQ) {
                float v = o[nc][j + 2] * linv_hi;
                float gl = 0.5f * v * (1.f + erff(v * 0.70710678118654752f));
                int flat = h * (NQ * HD) + n_hi * HD + d;
                int cc   = flat / NQ;
                int pos  = flat - cc * NQ;
                int kp   = cc >> 1;
                int sb   = (kp >> 3) * 4 + (kp & 3);
                int hi   = (kp >> 2) & 1;
                ap[(((size_t)b * 128 + sb) * NPAD + pos) * 4 + hi * 2 + (cc & 1)]
                    = __float2half_rn(gl);
            }
        }
    }
}

// ---------------------------------------------------------------------------
extern "C" void kernel_launch(void* const* d_in, const int* in_sizes, int n_in,
                              void* d_out, int out_size) {
    const float* x      = (const float*)d_in[0];
    const float* qkv_w  = (const float*)d_in[1];
    const float* bn1_g  = (const float*)d_in[2];
    const float* bn1_b  = (const float*)d_in[3];
    const float* bn1_m  = (const float*)d_in[4];
    const float* bn1_v  = (const float*)d_in[5];
    const float* proj_w = (const float*)d_in[6];
    const float* bn2_g  = (const float*)d_in[7];
    const float* bn2_b  = (const float*)d_in[8];
    const float* bn2_m  = (const float*)d_in[9];
    const float* bn2_v  = (const float*)d_in[10];
    const float* ab     = (const float*)d_in[11];
    const int*   idxs   = (const int*)d_in[12];
    float* out = (float*)d_out;

    const int smem_gemm = (2 * WS_T2 + 2 * XS_T2) * 8;            // 66560 B
    const int smem_attn = (KS_SZ + VS_SZ + 14 * PT_SZ) * 4;       // 156160 B
    cudaFuncSetAttribute(gemm_f16<0>,
                         cudaFuncAttributeMaxDynamicSharedMemorySize, smem_gemm);
    cudaFuncSetAttribute(gemm_f16<1>,
                         cudaFuncAttributeMaxDynamicSharedMemorySize, smem_gemm);
    cudaFuncSetAttribute(attn_kernel,
                         cudaFuncAttributeMaxDynamicSharedMemorySize, smem_attn);

    {   // convert weights to fp16 pair layout
        int total = 4 * CIN * CIN;
        cvt_w_kernel<<<(total + 255) / 256, 256>>>(qkv_w, proj_w);
    }
    {   // pad + convert x to fp16 pair layout
        int total = B_ * CIN * NQ;
        pad_cvt_x_kernel<<<(total + 255) / 256, 256>>>(x);
    }
    {   // bias gather
        int total = HEADS * NQ * NQ;
        gather_bias_kernel<<<(total + 255) / 256, 256>>>(ab, idxs);
    }
    {   // QKV GEMM + BN1 -> g_qkv (tf32 bits)
        dim3 grid(NPAD / 112, (3 * CIN) / 128, B_);
        gemm_f16<0><<<grid, 256, smem_gemm>>>(bn1_g, bn1_b, bn1_m, bn1_v, nullptr);
    }
    {   // attention + gelu + scrambled reshape
        attn_kernel<<<B_ * HEADS, 448, smem_attn>>>();
    }
    {   // proj GEMM + BN2 -> d_out
        dim3 grid(NPAD / 112, CIN / 128, B_);
        gemm_f16<1><<<grid, 256, smem_gemm>>>(bn2_g, bn2_b, bn2_m, bn2_v, out);
    }
}

// round 10
// speedup vs baseline: 5.3426x; 1.1559x over previous
#include <cuda_runtime.h>
#include <cuda_fp16.h>
#include <math.h>

// ---------------------------------------------------------------------------
// GlobalMHSAWithPosBias: B=128, C=512, RES=14 (N=196), HEADS=8, hd=64
// Round 10: fp16 mma everywhere. Attention now m16n8k16 fp16 with half2-pair
// smem layouts, 107 KB smem, 2 blocks/SM. g_qkv stored fp16.
// NOTE: never pass __device__ symbols from host code (rounds-3/4 bug).
// ---------------------------------------------------------------------------

#define B_    128
#define CIN   512
#define NQ    196
#define NPAD  224          // 4 * 56 = 2 * 112
#define HEADS 8
#define HD    64
#define EPS_  1e-5f

// fp16 GEMM operand layouts (round-9):
//  g_wh: uint2[pr][256 kp], pr = base + (o>>4)*8 + (o&7); .x=h2 W[o], .y=h2 W[o+8]
//  g_xh/g_att: half2 pairs, uint idx = ((b*128+sb)*224+n)*2 + hi,
//    sb=(kp>>3)*4+(kp&3), hi=(kp>>2)&1, halves by (c&1)
__device__ unsigned g_wh [(size_t)1024 * 256 * 2];
__device__ unsigned g_xh [(size_t)B_ * 128 * NPAD * 2];     // BSS 0 (pad cols)
__device__ unsigned g_att[(size_t)B_ * 128 * NPAD * 2];     // BSS 0
__device__ unsigned short g_qkv[(size_t)B_ * 3 * CIN * NPAD];  // fp16 halves
__device__ float    g_biasT[HEADS * NQ * NQ];

// ---------------------------------------------------------------------------
__device__ __forceinline__ void mma_f16(float c[4], const unsigned a[4],
                                        unsigned b0, unsigned b1) {
    asm volatile(
        "mma.sync.aligned.m16n8k16.row.col.f32.f16.f16.f32 "
        "{%0,%1,%2,%3}, {%4,%5,%6,%7}, {%8,%9}, {%0,%1,%2,%3};\n"
        : "+f"(c[0]), "+f"(c[1]), "+f"(c[2]), "+f"(c[3])
        : "r"(a[0]), "r"(a[1]), "r"(a[2]), "r"(a[3]), "r"(b0), "r"(b1));
}

__device__ __forceinline__ void cp16(void* dst, const void* src) {
    unsigned s = (unsigned)__cvta_generic_to_shared(dst);
    asm volatile("cp.async.cg.shared.global [%0], [%1], 16;" :: "r"(s), "l"(src));
}
__device__ __forceinline__ void cp_commit() {
    asm volatile("cp.async.commit_group;");
}
template <int N>
__device__ __forceinline__ void cp_wait() {
    asm volatile("cp.async.wait_group %0;" :: "n"(N));
}

__device__ __forceinline__ unsigned pack2(unsigned short lo, unsigned short hi) {
    return (unsigned)lo | ((unsigned)hi << 16);
}

// ---------------------------------------------------------------------------
// prologue converters
// ---------------------------------------------------------------------------
__global__ void cvt_w_kernel(const float* __restrict__ qkv_w,
                             const float* __restrict__ proj_w) {
    int i = blockIdx.x * blockDim.x + threadIdx.x;
    const int n1 = 3 * CIN * CIN, total = n1 + CIN * CIN;
    if (i >= total) return;
    float v;
    int o, k, basepr;
    if (i < n1) { v = qkv_w[i];       o = i / CIN;        k = i % CIN;        basepr = 0; }
    else        { v = proj_w[i - n1]; o = (i - n1) / CIN; k = (i - n1) % CIN; basepr = 768; }
    int pr   = basepr + (o >> 4) * 8 + (o & 7);
    int comp = (o >> 3) & 1;
    int kp   = k >> 1;
    ((__half*)g_wh)[(size_t)pr * 1024 + kp * 4 + comp * 2 + (k & 1)]
        = __float2half_rn(v);
}

// coalesced: one thread per output half2 (c-pair), gathers from x
__global__ void pad_cvt_x_kernel(const float* __restrict__ x) {
    int i = blockIdx.x * blockDim.x + threadIdx.x;
    const int total = B_ * 128 * NPAD * 2;
    if (i >= total) return;
    int hi = i & 1;
    int n  = (i >> 1) % NPAD;
    int r  = (i >> 1) / NPAD;          // b*128 + sb
    if (n >= NQ) return;               // pad cols stay 0 (BSS)
    int b  = r >> 7, sb = r & 127;
    int kp = (sb >> 2) * 8 + hi * 4 + (sb & 3);
    int c  = kp * 2;
    const float* xp = x + ((size_t)b * CIN + c) * NQ + n;
    __half2 h = __floats2half2_rn(xp[0], xp[NQ]);
    g_xh[((size_t)r * NPAD + n) * 2 + hi] = *(unsigned*)&h;
}

__global__ void gather_bias_kernel(const float* __restrict__ ab,
                                   const int*   __restrict__ idxs) {
    int i = blockIdx.x * blockDim.x + threadIdx.x;
    const int total = HEADS * NQ * NQ;
    if (i >= total) return;
    int stride = (idxs[1] == 0 && idxs[3] == 0) ? 2 : 1;   // int64 detection
    int h = i / (NQ * NQ);
    int j = i - h * (NQ * NQ);
    g_biasT[i] = ab[h * NQ + idxs[(size_t)j * stride]];
}

// ---------------------------------------------------------------------------
// fp16 GEMM + fused BN affine; pair-packed operands, cp.async 2-stage, BK=64.
// MODE 0: X=g_xh,  W pr base 0,   Y=g_qkv (fp16 halves, ldy=224)
// MODE 1: X=g_att, W pr base 768, Y=outp  (f32, ldy=196, guarded)
// ---------------------------------------------------------------------------
#define WP2 36
#define XP2 116
#define WS_T2 (64 * WP2)
#define XS_T2 (16 * XP2)

template <int MODE>
__global__ __launch_bounds__(256)
void gemm_f16(const float* __restrict__ gamma, const float* __restrict__ beta,
              const float* __restrict__ mean,  const float* __restrict__ var,
              float* __restrict__ outp) {
    extern __shared__ uint2 smg[];
    uint2* Ws = smg;
    uint2* Xs = smg + 2 * WS_T2;

    const uint2* __restrict__ X2 = (MODE == 0) ? (const uint2*)g_xh
                                               : (const uint2*)g_att;
    const uint2* __restrict__ W2 = (const uint2*)g_wh
                                   + (MODE == 0 ? 0 : (size_t)768 * 256);
    const int Ocnt = (MODE == 0) ? 3 * CIN : CIN;

    const int tid  = threadIdx.x;
    const int lane = tid & 31;
    const int wid  = tid >> 5;
    const int wm   = wid & 3;
    const int n0w  = (wid >> 2) * 56;

    const int b  = blockIdx.z;
    const int o0 = blockIdx.y * 128;
    const int n0 = blockIdx.x * 112;

    const uint2* __restrict__ Wp = W2 + (size_t)(o0 / 2) * 256;
    const uint2* __restrict__ Xp = X2 + ((size_t)b * 128) * NPAD + n0;

    float acc[2][7][4];
#pragma unroll
    for (int i = 0; i < 2; i++)
#pragma unroll
        for (int j = 0; j < 7; j++)
#pragma unroll
            for (int k = 0; k < 4; k++) acc[i][j][k] = 0.f;

    const int row = lane >> 2;
    const int col = lane & 3;

    auto load_tiles = [&](int it, int st) {
        uint2* ws = Ws + st * WS_T2;
        uint2* xs = Xs + st * XS_T2;
#pragma unroll
        for (int i = tid; i < 1024; i += 256) {
            int r = i >> 4, c2 = (i & 15) * 2;
            cp16(ws + r * WP2 + c2, Wp + (size_t)r * 256 + it * 32 + c2);
        }
#pragma unroll
        for (int i = tid; i < 896; i += 256) {
            int r = i / 56, c2 = (i % 56) * 2;
            cp16(xs + r * XP2 + c2, Xp + (size_t)(it * 16 + r) * NPAD + c2);
        }
        cp_commit();
    };

    load_tiles(0, 0);

    for (int it = 0; it < 8; ++it) {
        const int cur = it & 1;
        if (it + 1 < 8) {
            load_tiles(it + 1, (it + 1) & 1);
            cp_wait<1>();
        } else {
            cp_wait<0>();
        }
        __syncthreads();

        const uint2* ws = Ws + cur * WS_T2;
        const uint2* xs = Xs + cur * XS_T2;
#pragma unroll
        for (int ks = 0; ks < 4; ks++) {
            unsigned a[2][4];
#pragma unroll
            for (int mt = 0; mt < 2; mt++) {
                int pr = (wm * 2 + mt) * 8 + row;
                uint2 A01 = ws[pr * WP2 + ks * 8 + col];
                uint2 A23 = ws[pr * WP2 + ks * 8 + col + 4];
                a[mt][0] = A01.x; a[mt][1] = A01.y;
                a[mt][2] = A23.x; a[mt][3] = A23.y;
            }
#pragma unroll
            for (int nt = 0; nt < 7; nt++) {
                uint2 Bf = xs[(ks * 4 + col) * XP2 + n0w + nt * 8 + row];
                mma_f16(acc[0][nt], a[0], Bf.x, Bf.y);
                mma_f16(acc[1][nt], a[1], Bf.x, Bf.y);
            }
        }
        __syncthreads();
    }

#pragma unroll
    for (int mt = 0; mt < 2; mt++) {
        int o_a = o0 + wm * 32 + mt * 16 + row;
        int o_b = o_a + 8;
        float inv_a = gamma[o_a] * rsqrtf(var[o_a] + EPS_);
        float sh_a  = beta[o_a] - mean[o_a] * inv_a;
        float inv_b = gamma[o_b] * rsqrtf(var[o_b] + EPS_);
        float sh_b  = beta[o_b] - mean[o_b] * inv_b;
#pragma unroll
        for (int nt = 0; nt < 7; nt++) {
            int c0 = n0 + n0w + nt * 8 + col * 2;
            float y0 = acc[mt][nt][0] * inv_a + sh_a;
            float y1 = acc[mt][nt][1] * inv_a + sh_a;
            float y2 = acc[mt][nt][2] * inv_b + sh_b;
            float y3 = acc[mt][nt][3] * inv_b + sh_b;
            if (MODE == 0) {
                unsigned short* ya = g_qkv + ((size_t)b * Ocnt + o_a) * NPAD;
                unsigned short* yb = g_qkv + ((size_t)b * Ocnt + o_b) * NPAD;
                __half2 ha = __floats2half2_rn(y0, y1);
                __half2 hb = __floats2half2_rn(y2, y3);
                *(unsigned*)(ya + c0) = *(unsigned*)&ha;
                *(unsigned*)(yb + c0) = *(unsigned*)&hb;
            } else {
                float* ya = outp + ((size_t)b * Ocnt + o_a) * NQ;
                float* yb = outp + ((size_t)b * Ocnt + o_b) * NQ;
                if (c0 < NQ)     { ya[c0]     = y0; yb[c0]     = y2; }
                if (c0 + 1 < NQ) { ya[c0 + 1] = y1; yb[c0 + 1] = y3; }
            }
        }
    }
}

// ---------------------------------------------------------------------------
// fp16 tensor-core attention. One block per (b,h): 448 threads = 14 warps,
// 2 blocks/SM. Q,K smem half2-pairs-along-d [dp=32][m] pitch 232; V^T smem
// half2-pairs-along-m [mp=112][d] pitch 72; P per-warp half2 [16][20].
// S and PV via mma.m16n8k16.f16 (f32 accum). Exp-safe softmax; pad columns
// p=0; dead rows clamp bias row, never store.
// ---------------------------------------------------------------------------
#define KP2 232
#define VP2 72
#define PP2 20
#define AQS_O 0
#define AKS_O (32 * KP2)                 // 7424
#define AVS_O (2 * 32 * KP2)             // 14848
#define APT_O (AVS_O + 112 * VP2)        // 22912
#define ASM_WORDS (APT_O + 14 * 16 * PP2)   // 27392

__global__ __launch_bounds__(448, 2)
void attn_kernel() {
    extern __shared__ unsigned sm[];
    unsigned* Qs = sm + AQS_O;
    unsigned* Ks = sm + AKS_O;
    unsigned* Vs = sm + AVS_O;
    unsigned* Pt = sm + APT_O;

    const int tid  = threadIdx.x;
    const int lane = tid & 31;
    const int w    = tid >> 5;          // 0..13
    const int row  = lane >> 2;         // 0..7
    const int col  = lane & 3;          // 0..3
    const int b    = blockIdx.x >> 3;
    const int h    = blockIdx.x & 7;
    const int n0   = w * 16;

    const size_t base = ((size_t)b * 3 * CIN + h * HD) * NPAD;
    const unsigned short* __restrict__ Qh = g_qkv + base;
    const unsigned short* __restrict__ Kh = g_qkv + base + (size_t)CIN * NPAD;
    const unsigned short* __restrict__ Vh = g_qkv + base + (size_t)2 * CIN * NPAD;

    // stage Q,K: [dp][m] = h2(X[2dp][m], X[2dp+1][m])
    for (int i = tid; i < 32 * NPAD; i += 448) {
        int dp = i / NPAD, m = i - dp * NPAD;
        Qs[dp * KP2 + m] = pack2(Qh[(2 * dp) * NPAD + m], Qh[(2 * dp + 1) * NPAD + m]);
        Ks[dp * KP2 + m] = pack2(Kh[(2 * dp) * NPAD + m], Kh[(2 * dp + 1) * NPAD + m]);
    }
    // stage V^T: [mp][d] = h2(V[d][2mp], V[d][2mp+1])  (one aligned 4B load)
    for (int i = tid; i < 64 * 112; i += 448) {
        int d = i / 112, mp = i - d * 112;
        Vs[mp * VP2 + d] = *(const unsigned*)(Vh + (size_t)d * NPAD + 2 * mp);
    }
    __syncthreads();

    const float* __restrict__ bptr = g_biasT + (size_t)h * NQ * NQ;
    unsigned* ptw = Pt + w * 16 * PP2;
    const int nb_lo = min(n0 + row, NQ - 1);
    const int nb_hi = min(n0 + row + 8, NQ - 1);

    float o[8][4];
#pragma unroll
    for (int i = 0; i < 8; i++)
#pragma unroll
        for (int j = 0; j < 4; j++) o[i][j] = 0.f;
    float ll = 0.f, lh = 0.f;

    for (int mc = 0; mc < 7; mc++) {
        const int m0 = mc * 32;

        // ---- S = Q^T K for columns [m0, m0+32): 4 k16-steps over d ----
        float c[4][4];
#pragma unroll
        for (int s = 0; s < 4; s++)
#pragma unroll
            for (int j = 0; j < 4; j++) c[s][j] = 0.f;

#pragma unroll
        for (int t = 0; t < 4; t++) {
            const int qb = (t * 8 + col) * KP2 + n0 + row;
            unsigned a[4];
            a[0] = Qs[qb];
            a[1] = Qs[qb + 8];
            a[2] = Qs[qb + 4 * KP2];
            a[3] = Qs[qb + 4 * KP2 + 8];
#pragma unroll
            for (int s = 0; s < 4; s++) {
                const int kb = (t * 8 + col) * KP2 + m0 + s * 8 + row;
                mma_f16(c[s], a, Ks[kb], Ks[kb + 4 * KP2]);
            }
        }

        // exp + bias -> Pt (half2 pairs along m)
#pragma unroll
        for (int s = 0; s < 4; s++) {
            const int m_b = m0 + s * 8 + 2 * col;      // even; pair in/out together
            float p0 = 0.f, p1 = 0.f, p2 = 0.f, p3 = 0.f;
            if (m_b < NQ) {
                float2 blo = *(const float2*)(bptr + (size_t)nb_lo * NQ + m_b);
                float2 bhi = *(const float2*)(bptr + (size_t)nb_hi * NQ + m_b);
                p0 = __expf(c[s][0] * 0.125f + blo.x);
                p1 = __expf(c[s][1] * 0.125f + blo.y);
                p2 = __expf(c[s][2] * 0.125f + bhi.x);
                p3 = __expf(c[s][3] * 0.125f + bhi.y);
            }
            ll += p0 + p1;
            lh += p2 + p3;
            __half2 plo = __floats2half2_rn(p0, p1);
            __half2 phi = __floats2half2_rn(p2, p3);
            ptw[row * PP2 + s * 4 + col]       = *(unsigned*)&plo;
            ptw[(row + 8) * PP2 + s * 4 + col] = *(unsigned*)&phi;
        }
        __syncwarp();

        // ---- O += P V^T: 2 k16-steps over this m-chunk ----
#pragma unroll
        for (int u = 0; u < 2; u++) {
            unsigned a[4];
            a[0] = ptw[row * PP2 + u * 8 + col];
            a[1] = ptw[(row + 8) * PP2 + u * 8 + col];
            a[2] = ptw[row * PP2 + u * 8 + col + 4];
            a[3] = ptw[(row + 8) * PP2 + u * 8 + col + 4];
#pragma unroll
            for (int nc = 0; nc < 8; nc++) {
                const int vb = (mc * 16 + u * 8 + col) * VP2 + nc * 8 + row;
                mma_f16(o[nc], a, Vs[vb], Vs[vb + 4 * VP2]);
            }
        }
        __syncwarp();
    }

    // row sums across the quad
    ll += __shfl_xor_sync(0xffffffffu, ll, 1);
    ll += __shfl_xor_sync(0xffffffffu, ll, 2);
    lh += __shfl_xor_sync(0xffffffffu, lh, 1);
    lh += __shfl_xor_sync(0xffffffffu, lh, 2);
    const float linv_lo = 1.f / ll;
    const float linv_hi = 1.f / lh;

    __half* ap = (__half*)g_att;
    const int n_lo = n0 + row;
    const int n_hi = n0 + row + 8;
#pragma unroll
    for (int nc = 0; nc < 8; nc++) {
        int d0 = nc * 8 + 2 * col;
#pragma unroll
        for (int j = 0; j < 2; j++) {
            int d = d0 + j;
            if (n_lo < NQ) {
                float v = o[nc][j] * linv_lo;
                float gl = 0.5f * v * (1.f + erff(v * 0.70710678118654752f));
                int flat = h * (NQ * HD) + n_lo * HD + d;
                int cc   = flat / NQ;
                int pos  = flat - cc * NQ;
                int kp   = cc >> 1;
                int sb   = (kp >> 3) * 4 + (kp & 3);
                int hi   = (kp >> 2) & 1;
                ap[(((size_t)b * 128 + sb) * NPAD + pos) * 4 + hi * 2 + (cc & 1)]
                    = __float2half_rn(gl);
            }
            if (n_hi < NQ) {
                float v = o[nc][j + 2] * linv_hi;
                float gl = 0.5f * v * (1.f + erff(v * 0.70710678118654752f));
                int flat = h * (NQ * HD) + n_hi * HD + d;
                int cc   = flat / NQ;
                int pos  = flat - cc * NQ;
                int kp   = cc >> 1;
                int sb   = (kp >> 3) * 4 + (kp & 3);
                int hi   = (kp >> 2) & 1;
                ap[(((size_t)b * 128 + sb) * NPAD + pos) * 4 + hi * 2 + (cc & 1)]
                    = __float2half_rn(gl);
            }
        }
    }
}

// ---------------------------------------------------------------------------
extern "C" void kernel_launch(void* const* d_in, const int* in_sizes, int n_in,
                              void* d_out, int out_size) {
    const float* x      = (const float*)d_in[0];
    const float* qkv_w  = (const float*)d_in[1];
    const float* bn1_g  = (const float*)d_in[2];
    const float* bn1_b  = (const float*)d_in[3];
    const float* bn1_m  = (const float*)d_in[4];
    const float* bn1_v  = (const float*)d_in[5];
    const float* proj_w = (const float*)d_in[6];
    const float* bn2_g  = (const float*)d_in[7];
    const float* bn2_b  = (const float*)d_in[8];
    const float* bn2_m  = (const float*)d_in[9];
    const float* bn2_v  = (const float*)d_in[10];
    const float* ab     = (const float*)d_in[11];
    const int*   idxs   = (const int*)d_in[12];
    float* out = (float*)d_out;

    const int smem_gemm = (2 * WS_T2 + 2 * XS_T2) * 8;   // 66560 B
    const int smem_attn = ASM_WORDS * 4;                 // 109568 B
    cudaFuncSetAttribute(gemm_f16<0>,
                         cudaFuncAttributeMaxDynamicSharedMemorySize, smem_gemm);
    cudaFuncSetAttribute(gemm_f16<1>,
                         cudaFuncAttributeMaxDynamicSharedMemorySize, smem_gemm);
    cudaFuncSetAttribute(attn_kernel,
                         cudaFuncAttributeMaxDynamicSharedMemorySize, smem_attn);

    {   // convert weights to fp16 pair layout
        int total = 4 * CIN * CIN;
        cvt_w_kernel<<<(total + 255) / 256, 256>>>(qkv_w, proj_w);
    }
    {   // pad + convert x to fp16 pair layout (coalesced)
        int total = B_ * 128 * NPAD * 2;
        pad_cvt_x_kernel<<<(total + 255) / 256, 256>>>(x);
    }
    {   // bias gather
        int total = HEADS * NQ * NQ;
        gather_bias_kernel<<<(total + 255) / 256, 256>>>(ab, idxs);
    }
    {   // QKV GEMM + BN1 -> g_qkv (fp16)
        dim3 grid(NPAD / 112, (3 * CIN) / 128, B_);
        gemm_f16<0><<<grid, 256, smem_gemm>>>(bn1_g, bn1_b, bn1_m, bn1_v, nullptr);
    }
    {   // attention + gelu + scrambled reshape (fp16 tensor cores)
        attn_kernel<<<B_ * HEADS, 448, smem_attn>>>();
    }
    {   // proj GEMM + BN2 -> d_out
        dim3 grid(NPAD / 112, CIN / 128, B_);
        gemm_f16<1><<<grid, 256, smem_gemm>>>(bn2_g, bn2_b, bn2_m, bn2_v, out);
    }
}